// round 12
// baseline (speedup 1.0000x reference)
#include <cuda_runtime.h>
#include <math.h>
#include <stdint.h>

// ---------------- problem constants ----------------
#define B_    8
#define N_    4096      // tokens per batch (64x64)
#define C_    512
#define NH_   8         // heads
#define HD_   64        // head dim
#define SCALE 0.125f    // hd^-0.5

// ---------------- scratch (device globals; no allocation allowed) ----------------
__device__ float g_xhi   [B_*1024*C_];     //  16 MB  pooled tokens (tf32-rounded)
__device__ float g_qkv_hi[B_*1024*3*C_];   //  50 MB
__device__ float g_out_hi[B_*1024*C_];     //  16 MB
__device__ float g_win   [B_*N_*C_];       //  64 MB  window tokens (tf32-rounded)
__device__ float g_qkv_lo[B_*N_*3*C_];     // 201 MB
__device__ float g_comb  [B_*N_*C_];       //  64 MB  combined (tf32-rounded)
__device__ float g_wq_r  [3*C_*C_];        //   3 MB  Wqkv tf32-rounded
__device__ float g_wp_r  [C_*C_];          //   1 MB  Wproj tf32-rounded

// ======================= PTX helpers =======================
__device__ __forceinline__ uint32_t smem_u32(const void* p) {
    uint32_t a;
    asm("{ .reg .u64 t; cvta.to.shared.u64 t, %1; cvt.u32.u64 %0, t; }" : "=r"(a) : "l"(p));
    return a;
}
__device__ __forceinline__ float to_tf32(float x) {
    float r;
    asm("cvt.rna.tf32.f32 %0, %1;" : "=f"(r) : "f"(x));
    return r;
}

#define LDSM4(d0, d1, d2, d3, addr)                                            \
    asm volatile("ldmatrix.sync.aligned.m8n8.x4.shared.b16 {%0,%1,%2,%3}, [%4];" \
                 : "=r"(d0), "=r"(d1), "=r"(d2), "=r"(d3) : "r"(addr))

#define MMA_TF32(c, a, b)                                                      \
    asm volatile("mma.sync.aligned.m16n8k8.row.col.f32.tf32.tf32.f32 "         \
                 "{%0,%1,%2,%3}, {%4,%5,%6,%7}, {%8,%9}, {%0,%1,%2,%3};"       \
                 : "+f"((c)[0]), "+f"((c)[1]), "+f"((c)[2]), "+f"((c)[3])      \
                 : "r"((a)[0]), "r"((a)[1]), "r"((a)[2]), "r"((a)[3]),         \
                   "r"((b)[0]), "r"((b)[1]))

#define STSV4(addr, x, y, z, w)                                                \
    asm volatile("st.shared.v4.b32 [%0], {%1,%2,%3,%4};"                       \
                 :: "r"(addr), "f"(x), "f"(y), "f"(z), "f"(w) : "memory")
#define STSV2(addr, x, y)                                                      \
    asm volatile("st.shared.v2.b32 [%0], {%1,%2};"                             \
                 :: "r"(addr), "f"(x), "f"(y) : "memory")
#define STSB32(addr, x)                                                        \
    asm volatile("st.shared.b32 [%0], %1;" :: "r"(addr), "f"(x) : "memory")
#define LDSV4(x, y, z, w, addr)                                                \
    asm volatile("ld.shared.v4.b32 {%0,%1,%2,%3}, [%4];"                       \
                 : "=f"(x), "=f"(y), "=f"(z), "=f"(w) : "r"(addr))
#define CP_ASYNC16(dst, src)                                                   \
    asm volatile("cp.async.cg.shared.global [%0], [%1], 16;"                   \
                 :: "r"(dst), "l"(src) : "memory")
#define CP_COMMIT()  asm volatile("cp.async.commit_group;" ::: "memory")
#define CP_WAIT0()   asm volatile("cp.async.wait_group 0;" ::: "memory")
#define CP_WAIT1()   asm volatile("cp.async.wait_group 1;" ::: "memory")

// ======================= mma.sync tf32 GEMM v2 (unchanged) =======================
#define GEMM_SMEM (1024 + 65536)

template <bool BIAS>
__global__ void __launch_bounds__(256, 2) mma_gemm(
    const float* __restrict__ A, const float* __restrict__ Bm,
    const float* __restrict__ bias, float* __restrict__ Cm,
    int M, int N, int K)
{
    extern __shared__ char dsm[];
    uint32_t sb = (smem_u32(dsm) + 1023u) & ~1023u;

    const int t = threadIdx.x;
    const int bm = blockIdx.y, bn = blockIdx.x;
    const int lane = t & 31, wid = t >> 5;
    const int warp_m = wid & 1, warp_n = wid >> 1;

    const int f4 = t & 7;
    const int row0 = t >> 3;
    const float* Ap = A  + (long)(bm * 128 + row0) * K + f4 * 4;
    const float* Bp = Bm + (long)(bn * 128 + row0) * K + f4 * 4;
    uint32_t stOff[4];
#pragma unroll
    for (int g = 0; g < 4; g++) {
        uint32_t off = (row0 + 32 * g) * 128 + f4 * 16;
        stOff[g] = off ^ ((off >> 3) & 0x70);
    }

    const int l = lane & 7, g8 = lane >> 3;
    const int aRow = warp_m * 64 + (g8 & 1) * 8 + l;
    const uint32_t aSw   = (uint32_t)((aRow & 7) << 4);
    const uint32_t aKoff = (uint32_t)((g8 >> 1) * 16);
    const int bRow = warp_n * 32 + (g8 >> 1) * 8 + l;
    const uint32_t bSw   = (uint32_t)((bRow & 7) << 4);
    const uint32_t bKoff = (uint32_t)((g8 & 1) * 16);

    float acc[4][4][4];
#pragma unroll
    for (int mi = 0; mi < 4; mi++)
#pragma unroll
        for (int ni = 0; ni < 4; ni++)
#pragma unroll
            for (int q = 0; q < 4; q++) acc[mi][ni][q] = 0.f;

    const int KC = K >> 5;
    {
        uint32_t sA = sb, sB = sb + 16384;
#pragma unroll
        for (int g = 0; g < 4; g++) {
            CP_ASYNC16(sA + stOff[g], Ap + (long)(g * 32) * K);
            CP_ASYNC16(sB + stOff[g], Bp + (long)(g * 32) * K);
        }
        CP_COMMIT();
    }

    for (int c = 0; c < KC; c++) {
        if (c + 1 < KC) {
            uint32_t sA = sb + ((c + 1) & 1) * 32768, sB = sA + 16384;
            const float* An = Ap + (c + 1) * 32;
            const float* Bn = Bp + (c + 1) * 32;
#pragma unroll
            for (int g = 0; g < 4; g++) {
                CP_ASYNC16(sA + stOff[g], An + (long)(g * 32) * K);
                CP_ASYNC16(sB + stOff[g], Bn + (long)(g * 32) * K);
            }
            CP_COMMIT();
            CP_WAIT1();
        } else {
            CP_WAIT0();
        }
        __syncthreads();

        uint32_t bufA = sb + (c & 1) * 32768;
        uint32_t bufB = bufA + 16384;
#pragma unroll
        for (int kk = 0; kk < 4; kk++) {
            uint32_t aOff = ((uint32_t)(kk * 32) + aKoff) ^ aSw;
            uint32_t bOff = ((uint32_t)(kk * 32) + bKoff) ^ bSw;
            uint32_t af[4][4], bf[4][2];
#pragma unroll
            for (int mi = 0; mi < 4; mi++)
                LDSM4(af[mi][0], af[mi][1], af[mi][2], af[mi][3],
                      bufA + (uint32_t)((aRow + mi * 16) * 128) + aOff);
#pragma unroll
            for (int j = 0; j < 2; j++) {
                uint32_t r0, r1, r2, r3;
                LDSM4(r0, r1, r2, r3,
                      bufB + (uint32_t)((bRow + j * 16) * 128) + bOff);
                bf[2 * j][0] = r0;     bf[2 * j][1] = r1;
                bf[2 * j + 1][0] = r2; bf[2 * j + 1][1] = r3;
            }
#pragma unroll
            for (int mi = 0; mi < 4; mi++)
#pragma unroll
                for (int ni = 0; ni < 4; ni++)
                    MMA_TF32(acc[mi][ni], af[mi], bf[ni]);
        }
        __syncthreads();
    }

    const int qr = lane >> 2, qc = lane & 3;
#pragma unroll
    for (int mi = 0; mi < 4; mi++) {
        int row = bm * 128 + warp_m * 64 + mi * 16 + qr;
#pragma unroll
        for (int ni = 0; ni < 4; ni++) {
            int col = bn * 128 + warp_n * 32 + ni * 8 + qc * 2;
            float bx = 0.f, by = 0.f;
            if (BIAS) { float2 b2 = *(const float2*)&bias[col]; bx = b2.x; by = b2.y; }
            *(float2*)&Cm[(long)row * N + col] =
                make_float2(acc[mi][ni][0] + bx, acc[mi][ni][1] + by);
            *(float2*)&Cm[(long)(row + 8) * N + col] =
                make_float2(acc[mi][ni][2] + bx, acc[mi][ni][3] + by);
        }
    }
}

// ---------------- weight rounding (Wqkv + Wproj -> tf32) ----------------
__global__ void round_w_kernel(const float* __restrict__ wq, const float* __restrict__ wp) {
    int i = blockIdx.x * blockDim.x + threadIdx.x;
    if (i < 196608) {
        float4 v = ((const float4*)wq)[i];
        ((float4*)g_wq_r)[i] = make_float4(to_tf32(v.x), to_tf32(v.y), to_tf32(v.z), to_tf32(v.w));
    } else {
        float4 v = ((const float4*)wp)[i - 196608];
        ((float4*)g_wp_r)[i - 196608] = make_float4(to_tf32(v.x), to_tf32(v.y), to_tf32(v.z), to_tf32(v.w));
    }
}

// ---------------- prep v2: vectorized avg-pool + window gather ----------------
__global__ void __launch_bounds__(256) prep_kernel(const float* __restrict__ x) {
    int id = blockIdx.x * blockDim.x + threadIdx.x;   // 8*1024*128 = 1M threads
    int c4 = (id & 127) << 2;
    int w  = (id >> 7) & 1023;
    int b  = id >> 17;
    int hh = w >> 5, wh = w & 31;

    long r0 = (long)(b * 4096 + (2 * hh) * 64 + 2 * wh) * 512 + c4;
    float4 a00 = *(const float4*)&x[r0];
    float4 a01 = *(const float4*)&x[r0 + 512];
    float4 a10 = *(const float4*)&x[r0 + 64 * 512];
    float4 a11 = *(const float4*)&x[r0 + 65 * 512];

    float4 pool;
    pool.x = to_tf32(0.25f * (a00.x + a01.x + a10.x + a11.x));
    pool.y = to_tf32(0.25f * (a00.y + a01.y + a10.y + a11.y));
    pool.z = to_tf32(0.25f * (a00.z + a01.z + a10.z + a11.z));
    pool.w = to_tf32(0.25f * (a00.w + a01.w + a10.w + a11.w));
    *(float4*)&g_xhi[(long)(b * 1024 + w) * 512 + c4] = pool;

    int t = c4 >> 7;
    int c = (4 * c4) & 511;
    float* wr = &g_win[(long)((b * 1024 + w) * 4 + t) * 512 + c];
    *(float4*)(wr + 0)  = make_float4(to_tf32(a00.x), to_tf32(a01.x), to_tf32(a10.x), to_tf32(a11.x));
    *(float4*)(wr + 4)  = make_float4(to_tf32(a00.y), to_tf32(a01.y), to_tf32(a10.y), to_tf32(a11.y));
    *(float4*)(wr + 8)  = make_float4(to_tf32(a00.z), to_tf32(a01.z), to_tf32(a10.z), to_tf32(a11.z));
    *(float4*)(wr + 12) = make_float4(to_tf32(a00.w), to_tf32(a01.w), to_tf32(a10.w), to_tf32(a11.w));
}

// ======================= flash attention v7: Br=64, 128 threads, co-residable =======================
// grid (16 q-tiles, 64 bh), 128 threads = 4 warps; warp w owns q-rows 16w..16w+15.
// Small footprint (26K regs + 84KB smem) so a GEMM block (33K regs + 66KB) can co-reside.
// v6 machinery retained: Q-in-registers, cp.async KV pipeline, no-max softmax.
// smem: KH 16K | V^T 16K | P 16K | rawK 17408 | rawV 17408
#define RAWK_OFF 49152
#define RAWV_OFF (49152 + 17408)
#define FLASH_SMEM (49152 + 2 * 17408 + 2048)

__global__ void __launch_bounds__(128, 1) flash_hi_tc() {
    extern __shared__ char fsm[];
    uint32_t sb = (smem_u32(fsm) + 1023u) & ~1023u;
    const uint32_t KH = sb, VS = sb + 16384, PS = sb + 32768;
    const uint32_t RK = sb + RAWK_OFF, RV = sb + RAWV_OFF;

    const int t = threadIdx.x, lane = t & 31, wid = t >> 5;
    const int qt = blockIdx.x, bh = blockIdx.y;
    const int b = bh >> 3, h = bh & 7;

    // staging geometry (128 threads, 64-token tiles)
    const int krow = t >> 1, kh2 = t & 1;            // K: 64 rows x 2 half-rows(128B)
    const int vtok = t & 63, vdh = (t >> 6) * 32;    // V: 64 toks x 2 d-halves
    const uint32_t rkd = RK + (uint32_t)(krow * 272 + kh2 * 128);
    const uint32_t rvd = RV + (uint32_t)(vtok * 272 + vdh * 4);
    const float* kv_base = g_qkv_hi + (long)(b * 1024) * 1536 + 512 + h * 64;

    // issue tile 0 copy
    {
        const float* kg = kv_base + (long)krow * 1536 + kh2 * 32;
        const float* vg = kv_base + (long)vtok * 1536 + 512 + vdh;
#pragma unroll
        for (int i = 0; i < 8; i++) {
            CP_ASYNC16(rkd + i * 16, kg + i * 4);
            CP_ASYNC16(rvd + i * 16, vg + i * 4);
        }
        CP_COMMIT();
    }

    // ---- fragment geometry ----
    const int l7 = lane & 7, g8 = lane >> 3;
    const int aRow = wid * 16 + (g8 & 1) * 8 + l7;   // q rows 0..63
    const uint32_t aKsel = (uint32_t)((g8 >> 1) * 16);
    const int bRow = (g8 >> 1) * 8 + l7;
    const uint32_t bKsel = (uint32_t)((g8 & 1) * 16);
    const uint32_t swl = (uint32_t)(l7 << 4);
    const uint32_t aBase = (uint32_t)(aRow * 256);
    const int qr = lane >> 2, qc = lane & 3;

    // ---- load Q fragments into registers (KH as scratch) ----
    uint32_t qh[8][4];
    {
        int row = t >> 1, hb = t & 1;
        const float* qg = g_qkv_hi + (long)(b * 1024 + qt * 64 + row) * 1536 + h * 64 + hb * 32;
        uint32_t rbase = (uint32_t)(row * 256);
        uint32_t rsw = (uint32_t)((row & 7) << 4);
#pragma unroll
        for (int i = 0; i < 8; i++) {
            float4 v = *(const float4*)(qg + i * 4);
            v.x *= SCALE; v.y *= SCALE; v.z *= SCALE; v.w *= SCALE;
            uint32_t off = ((uint32_t)(hb * 128 + i * 16)) ^ rsw;
            STSV4(KH + rbase + off, to_tf32(v.x), to_tf32(v.y), to_tf32(v.z), to_tf32(v.w));
        }
        __syncthreads();
#pragma unroll
        for (int kk = 0; kk < 8; kk++)
            LDSM4(qh[kk][0], qh[kk][1], qh[kk][2], qh[kk][3],
                  KH + aBase + (((uint32_t)(kk * 32) + aKsel) ^ swl));
    }

    float oacc[8][4];
#pragma unroll
    for (int ni = 0; ni < 8; ni++)
#pragma unroll
        for (int q = 0; q < 4; q++) oacc[ni][q] = 0.f;
    float l0 = 0.f, l1 = 0.f;

    for (int kt = 0; kt < 16; kt++) {
        CP_WAIT0();
        __syncthreads();   // raw tile kt visible; prior readers of KH/VS done

        // ---- convert raw K -> KH ----
        {
            uint32_t rbase = (uint32_t)(krow * 256);
            uint32_t rsw = (uint32_t)((krow & 7) << 4);
#pragma unroll
            for (int i = 0; i < 8; i++) {
                float x_, y_, z_, w_;
                LDSV4(x_, y_, z_, w_, rkd + i * 16);
                uint32_t off = ((uint32_t)(kh2 * 128 + i * 16)) ^ rsw;
                STSV4(KH + rbase + off, to_tf32(x_), to_tf32(y_), to_tf32(z_), to_tf32(w_));
            }
        }
        // ---- convert raw V -> V^T (lane-distinct tokens: conflict-free) ----
        {
            uint32_t tokb = (uint32_t)(vtok * 4);
#pragma unroll
            for (int i = 0; i < 8; i++) {
                float x_, y_, z_, w_;
                LDSV4(x_, y_, z_, w_, rvd + i * 16);
                int d0 = vdh + i * 4;
                STSB32(VS + (uint32_t)((d0 + 0) * 256) + (tokb ^ (uint32_t)(((d0 + 0) & 7) << 4)), to_tf32(x_));
                STSB32(VS + (uint32_t)((d0 + 1) * 256) + (tokb ^ (uint32_t)(((d0 + 1) & 7) << 4)), to_tf32(y_));
                STSB32(VS + (uint32_t)((d0 + 2) * 256) + (tokb ^ (uint32_t)(((d0 + 2) & 7) << 4)), to_tf32(z_));
                STSB32(VS + (uint32_t)((d0 + 3) * 256) + (tokb ^ (uint32_t)(((d0 + 3) & 7) << 4)), to_tf32(w_));
            }
        }
        // ---- issue copy for tile kt+1 ----
        if (kt + 1 < 16) {
            const float* kg = kv_base + (long)((kt + 1) * 64 + krow) * 1536 + kh2 * 32;
            const float* vg = kv_base + (long)((kt + 1) * 64 + vtok) * 1536 + 512 + vdh;
#pragma unroll
            for (int i = 0; i < 8; i++) {
                CP_ASYNC16(rkd + i * 16, kg + i * 4);
                CP_ASYNC16(rvd + i * 16, vg + i * 4);
            }
            CP_COMMIT();
        }
        __syncthreads();

        // ---- S = Q K^T ----
        float sacc[8][4];
#pragma unroll
        for (int ni = 0; ni < 8; ni++)
#pragma unroll
            for (int q = 0; q < 4; q++) sacc[ni][q] = 0.f;

#pragma unroll
        for (int kk = 0; kk < 8; kk++) {
            uint32_t bOff = ((uint32_t)(kk * 32) + bKsel) ^ swl;
#pragma unroll
            for (int j = 0; j < 4; j++) {
                uint32_t r0, r1, r2, r3;
                LDSM4(r0, r1, r2, r3, KH + (uint32_t)((bRow + j * 16) * 256) + bOff);
                uint32_t bh0[2] = {r0, r1}, bh1[2] = {r2, r3};
                MMA_TF32(sacc[2 * j],     qh[kk], bh0);
                MMA_TF32(sacc[2 * j + 1], qh[kk], bh1);
            }
        }

        // ---- P = exp(S) directly (no-max softmax; logits bounded) ----
        float rs0 = 0.f, rs1 = 0.f;
        const uint32_t pr0 = PS + (uint32_t)((wid * 16 + qr) * 256);
        const uint32_t pr1 = PS + (uint32_t)((wid * 16 + qr + 8) * 256);
        const uint32_t sw0 = (uint32_t)((qr & 7) << 4);
        const uint32_t sw1 = (uint32_t)(((qr + 8) & 7) << 4);
#pragma unroll
        for (int ni = 0; ni < 8; ni++) {
            float q0 = to_tf32(__expf(sacc[ni][0]));
            float q1 = to_tf32(__expf(sacc[ni][1]));
            float q2 = to_tf32(__expf(sacc[ni][2]));
            float q3 = to_tf32(__expf(sacc[ni][3]));
            rs0 += q0 + q1; rs1 += q2 + q3;
            uint32_t cb = (uint32_t)(ni * 32 + qc * 8);
            STSV2(pr0 + (cb ^ sw0), q0, q1);
            STSV2(pr1 + (cb ^ sw1), q2, q3);
        }
        rs0 += __shfl_xor_sync(0xffffffffu, rs0, 1);
        rs0 += __shfl_xor_sync(0xffffffffu, rs0, 2);
        rs1 += __shfl_xor_sync(0xffffffffu, rs1, 1);
        rs1 += __shfl_xor_sync(0xffffffffu, rs1, 2);
        l0 += rs0; l1 += rs1;
        __syncwarp();   // P rows are warp-private

        // ---- O += P V ----
#pragma unroll
        for (int kk = 0; kk < 8; kk++) {
            uint32_t kb = (uint32_t)(kk * 32);
            uint32_t ap[4];
            LDSM4(ap[0], ap[1], ap[2], ap[3], PS + aBase + ((kb + aKsel) ^ swl));
            uint32_t bOff = (kb + bKsel) ^ swl;
#pragma unroll
            for (int j = 0; j < 4; j++) {
                uint32_t r0, r1, r2, r3;
                LDSM4(r0, r1, r2, r3, VS + (uint32_t)((bRow + j * 16) * 256) + bOff);
                uint32_t bv0[2] = {r0, r1}, bv1[2] = {r2, r3};
                MMA_TF32(oacc[2 * j],     ap, bv0);
                MMA_TF32(oacc[2 * j + 1], ap, bv1);
            }
        }
    }

    float inv0 = 1.f / l0, inv1 = 1.f / l1;
    long r0g = (long)(b * 1024 + qt * 64 + wid * 16 + qr) * 512 + h * 64;
    long r1g = r0g + 8 * 512;
#pragma unroll
    for (int ni = 0; ni < 8; ni++) {
        int col = ni * 8 + qc * 2;
        *(float2*)&g_out_hi[r0g + col] = make_float2(oacc[ni][0] * inv0, oacc[ni][1] * inv0);
        *(float2*)&g_out_hi[r1g + col] = make_float2(oacc[ni][2] * inv1, oacc[ni][3] * inv1);
    }
}

// ---------------- lo-branch windowed attention + fused hi upsample-add ----------------
__global__ void __launch_bounds__(256) lo_attn_kernel() {
    int gid  = blockIdx.x * blockDim.x + threadIdx.x;
    int warp = gid >> 5;
    int lane = gid & 31;
    int h = warp & 7;
    int w = (warp >> 3) & 1023;
    int b = warp >> 13;

    const float* base = g_qkv_lo + (long)((b * 1024 + w) * 4) * 1536 + h * 64 + 2 * lane;
    float2 q[4], k[4], v[4];
#pragma unroll
    for (int t = 0; t < 4; t++) {
        q[t] = *(const float2*)(base + (long)t * 1536);
        k[t] = *(const float2*)(base + (long)t * 1536 + 512);
        v[t] = *(const float2*)(base + (long)t * 1536 + 1024);
    }

    float lg[4][4];
#pragma unroll
    for (int ti = 0; ti < 4; ti++)
#pragma unroll
        for (int tj = 0; tj < 4; tj++) {
            float p = q[ti].x * k[tj].x + q[ti].y * k[tj].y;
            p += __shfl_xor_sync(0xffffffffu, p, 16);
            p += __shfl_xor_sync(0xffffffffu, p, 8);
            p += __shfl_xor_sync(0xffffffffu, p, 4);
            p += __shfl_xor_sync(0xffffffffu, p, 2);
            p += __shfl_xor_sync(0xffffffffu, p, 1);
            lg[ti][tj] = p * SCALE;
        }

    int hh = w >> 5, wh = w & 31;
    long hibase = (long)b * 1024 * 512;
    int ccol = h * 64 + 2 * lane;
#pragma unroll
    for (int ti = 0; ti < 4; ti++) {
        float mx = fmaxf(fmaxf(lg[ti][0], lg[ti][1]), fmaxf(lg[ti][2], lg[ti][3]));
        float e0 = __expf(lg[ti][0] - mx);
        float e1 = __expf(lg[ti][1] - mx);
        float e2 = __expf(lg[ti][2] - mx);
        float e3 = __expf(lg[ti][3] - mx);
        float is = 1.f / (e0 + e1 + e2 + e3);
        float ox = (e0 * v[0].x + e1 * v[1].x + e2 * v[2].x + e3 * v[3].x) * is;
        float oy = (e0 * v[0].y + e1 * v[1].y + e2 * v[2].y + e3 * v[3].y) * is;

        int y  = 2 * hh + (ti >> 1);
        int xq = 2 * wh + (ti & 1);
        float sy = 0.5f * y - 0.25f;
        int   y0 = (int)floorf(sy);
        float fy = sy - (float)y0;
        int   y1 = min(y0 + 1, 31); y0 = max(y0, 0);
        float sx = 0.5f * xq - 0.25f;
        int   x0 = (int)floorf(sx);
        float fx = sx - (float)x0;
        int   x1 = min(x0 + 1, 31); x0 = max(x0, 0);
        float w00 = (1.f - fy) * (1.f - fx), w01 = (1.f - fy) * fx;
        float w10 = fy * (1.f - fx),         w11 = fy * fx;

        float2 v00 = *(const float2*)&g_out_hi[hibase + (long)(y0 * 32 + x0) * 512 + ccol];
        float2 v01 = *(const float2*)&g_out_hi[hibase + (long)(y0 * 32 + x1) * 512 + ccol];
        float2 v10 = *(const float2*)&g_out_hi[hibase + (long)(y1 * 32 + x0) * 512 + ccol];
        float2 v11 = *(const float2*)&g_out_hi[hibase + (long)(y1 * 32 + x1) * 512 + ccol];
        float hx = w00 * v00.x + w01 * v01.x + w10 * v10.x + w11 * v11.x;
        float hy = w00 * v00.y + w01 * v01.y + w10 * v10.y + w11 * v11.y;

        int pos = y * 64 + xq;
        *(float2*)&g_comb[(long)(b * 4096 + pos) * 512 + ccol] =
            make_float2(to_tf32(ox + hx), to_tf32(oy + hy));
    }
}

// ---------------- launch (dual-stream overlap; flash now co-residable with GEMM) ----------------
extern "C" void kernel_launch(void* const* d_in, const int* in_sizes, int n_in,
                              void* d_out, int out_size) {
    const float* x     = (const float*)d_in[0];
    const float* Wqkv  = (const float*)d_in[1];
    const float* Wproj = (const float*)d_in[2];
    const float* bproj = (const float*)d_in[3];
    float* out = (float*)d_out;

    float *xhi, *qkvhi, *win, *qkvlo, *comb, *wqr, *wpr;
    cudaGetSymbolAddress((void**)&xhi,   g_xhi);
    cudaGetSymbolAddress((void**)&qkvhi, g_qkv_hi);
    cudaGetSymbolAddress((void**)&win,   g_win);
    cudaGetSymbolAddress((void**)&qkvlo, g_qkv_lo);
    cudaGetSymbolAddress((void**)&comb,  g_comb);
    cudaGetSymbolAddress((void**)&wqr,   g_wq_r);
    cudaGetSymbolAddress((void**)&wpr,   g_wp_r);

    cudaFuncSetAttribute(mma_gemm<false>, cudaFuncAttributeMaxDynamicSharedMemorySize, GEMM_SMEM);
    cudaFuncSetAttribute(mma_gemm<true>,  cudaFuncAttributeMaxDynamicSharedMemorySize, GEMM_SMEM);
    cudaFuncSetAttribute(flash_hi_tc,     cudaFuncAttributeMaxDynamicSharedMemorySize, FLASH_SMEM);

    static cudaStream_t s2 = nullptr;
    static cudaEvent_t evFork = nullptr, evJoin = nullptr;
    if (s2 == nullptr) {
        cudaStreamCreateWithFlags(&s2, cudaStreamNonBlocking);
        cudaEventCreateWithFlags(&evFork, cudaEventDisableTiming);
        cudaEventCreateWithFlags(&evJoin, cudaEventDisableTiming);
    }

    // 0. weight rounding + prep (main stream)
    round_w_kernel<<<1024, 256>>>(Wqkv, Wproj);
    prep_kernel<<<4096, 256>>>(x);

    // fork: lo QKV GEMM on side stream
    cudaEventRecord(evFork, 0);
    cudaStreamWaitEvent(s2, evFork, 0);
    mma_gemm<false><<<dim3(12, 256), 256, GEMM_SMEM, s2>>>(win, wqr, nullptr, qkvlo, 32768, 1536, 512);
    cudaEventRecord(evJoin, s2);

    // main stream: hi QKV GEMM -> flash attention (co-resides with lo GEMM blocks)
    mma_gemm<false><<<dim3(12, 64), 256, GEMM_SMEM>>>(xhi, wqr, nullptr, qkvhi, 8192, 1536, 512);
    flash_hi_tc<<<dim3(16, 64), 128, FLASH_SMEM>>>();

    // join, then lo attention (+ upsample-add) and output projection
    cudaStreamWaitEvent(0, evJoin, 0);
    lo_attn_kernel<<<8192, 256>>>();
    mma_gemm<true><<<dim3(4, 256), 256, GEMM_SMEM>>>(comb, wpr, bproj, out, 32768, 512, 512);
}

// round 13
// speedup vs baseline: 1.0892x; 1.0892x over previous
#include <cuda_runtime.h>
#include <math.h>
#include <stdint.h>

// ---------------- problem constants ----------------
#define B_    8
#define N_    4096      // tokens per batch (64x64)
#define C_    512
#define NH_   8         // heads
#define HD_   64        // head dim
#define SCALE 0.125f    // hd^-0.5

// ---------------- scratch (device globals; no allocation allowed) ----------------
__device__ float g_xhi   [B_*1024*C_];     //  16 MB  pooled tokens (tf32-rounded)
__device__ float g_qkv_hi[B_*1024*3*C_];   //  50 MB
__device__ float g_out_hi[B_*1024*C_];     //  16 MB
__device__ float g_win   [B_*N_*C_];       //  64 MB  window tokens (tf32-rounded)
__device__ float g_qkv_lo[B_*N_*3*C_];     // 201 MB
__device__ float g_comb  [B_*N_*C_];       //  64 MB  out_lo, then out_lo+hi (tf32)
__device__ float g_wq_r  [3*C_*C_];        //   3 MB  Wqkv tf32-rounded
__device__ float g_wp_r  [C_*C_];          //   1 MB  Wproj tf32-rounded

// ======================= PTX helpers =======================
__device__ __forceinline__ uint32_t smem_u32(const void* p) {
    uint32_t a;
    asm("{ .reg .u64 t; cvta.to.shared.u64 t, %1; cvt.u32.u64 %0, t; }" : "=r"(a) : "l"(p));
    return a;
}
__device__ __forceinline__ float to_tf32(float x) {
    float r;
    asm("cvt.rna.tf32.f32 %0, %1;" : "=f"(r) : "f"(x));
    return r;
}

#define LDSM4(d0, d1, d2, d3, addr)                                            \
    asm volatile("ldmatrix.sync.aligned.m8n8.x4.shared.b16 {%0,%1,%2,%3}, [%4];" \
                 : "=r"(d0), "=r"(d1), "=r"(d2), "=r"(d3) : "r"(addr))

#define MMA_TF32(c, a, b)                                                      \
    asm volatile("mma.sync.aligned.m16n8k8.row.col.f32.tf32.tf32.f32 "         \
                 "{%0,%1,%2,%3}, {%4,%5,%6,%7}, {%8,%9}, {%0,%1,%2,%3};"       \
                 : "+f"((c)[0]), "+f"((c)[1]), "+f"((c)[2]), "+f"((c)[3])      \
                 : "r"((a)[0]), "r"((a)[1]), "r"((a)[2]), "r"((a)[3]),         \
                   "r"((b)[0]), "r"((b)[1]))

#define STSV4(addr, x, y, z, w)                                                \
    asm volatile("st.shared.v4.b32 [%0], {%1,%2,%3,%4};"                       \
                 :: "r"(addr), "f"(x), "f"(y), "f"(z), "f"(w) : "memory")
#define STSV2(addr, x, y)                                                      \
    asm volatile("st.shared.v2.b32 [%0], {%1,%2};"                             \
                 :: "r"(addr), "f"(x), "f"(y) : "memory")
#define STSB32(addr, x)                                                        \
    asm volatile("st.shared.b32 [%0], %1;" :: "r"(addr), "f"(x) : "memory")
#define LDSV4(x, y, z, w, addr)                                                \
    asm volatile("ld.shared.v4.b32 {%0,%1,%2,%3}, [%4];"                       \
                 : "=f"(x), "=f"(y), "=f"(z), "=f"(w) : "r"(addr))
#define CP_ASYNC16(dst, src)                                                   \
    asm volatile("cp.async.cg.shared.global [%0], [%1], 16;"                   \
                 :: "r"(dst), "l"(src) : "memory")
#define CP_COMMIT()  asm volatile("cp.async.commit_group;" ::: "memory")
#define CP_WAIT0()   asm volatile("cp.async.wait_group 0;" ::: "memory")
#define CP_WAIT1()   asm volatile("cp.async.wait_group 1;" ::: "memory")

// ======================= mma.sync tf32 GEMM v2 (unchanged) =======================
#define GEMM_SMEM (1024 + 65536)

template <bool BIAS>
__global__ void __launch_bounds__(256, 2) mma_gemm(
    const float* __restrict__ A, const float* __restrict__ Bm,
    const float* __restrict__ bias, float* __restrict__ Cm,
    int M, int N, int K)
{
    extern __shared__ char dsm[];
    uint32_t sb = (smem_u32(dsm) + 1023u) & ~1023u;

    const int t = threadIdx.x;
    const int bm = blockIdx.y, bn = blockIdx.x;
    const int lane = t & 31, wid = t >> 5;
    const int warp_m = wid & 1, warp_n = wid >> 1;

    const int f4 = t & 7;
    const int row0 = t >> 3;
    const float* Ap = A  + (long)(bm * 128 + row0) * K + f4 * 4;
    const float* Bp = Bm + (long)(bn * 128 + row0) * K + f4 * 4;
    uint32_t stOff[4];
#pragma unroll
    for (int g = 0; g < 4; g++) {
        uint32_t off = (row0 + 32 * g) * 128 + f4 * 16;
        stOff[g] = off ^ ((off >> 3) & 0x70);
    }

    const int l = lane & 7, g8 = lane >> 3;
    const int aRow = warp_m * 64 + (g8 & 1) * 8 + l;
    const uint32_t aSw   = (uint32_t)((aRow & 7) << 4);
    const uint32_t aKoff = (uint32_t)((g8 >> 1) * 16);
    const int bRow = warp_n * 32 + (g8 >> 1) * 8 + l;
    const uint32_t bSw   = (uint32_t)((bRow & 7) << 4);
    const uint32_t bKoff = (uint32_t)((g8 & 1) * 16);

    float acc[4][4][4];
#pragma unroll
    for (int mi = 0; mi < 4; mi++)
#pragma unroll
        for (int ni = 0; ni < 4; ni++)
#pragma unroll
            for (int q = 0; q < 4; q++) acc[mi][ni][q] = 0.f;

    const int KC = K >> 5;
    {
        uint32_t sA = sb, sB = sb + 16384;
#pragma unroll
        for (int g = 0; g < 4; g++) {
            CP_ASYNC16(sA + stOff[g], Ap + (long)(g * 32) * K);
            CP_ASYNC16(sB + stOff[g], Bp + (long)(g * 32) * K);
        }
        CP_COMMIT();
    }

    for (int c = 0; c < KC; c++) {
        if (c + 1 < KC) {
            uint32_t sA = sb + ((c + 1) & 1) * 32768, sB = sA + 16384;
            const float* An = Ap + (c + 1) * 32;
            const float* Bn = Bp + (c + 1) * 32;
#pragma unroll
            for (int g = 0; g < 4; g++) {
                CP_ASYNC16(sA + stOff[g], An + (long)(g * 32) * K);
                CP_ASYNC16(sB + stOff[g], Bn + (long)(g * 32) * K);
            }
            CP_COMMIT();
            CP_WAIT1();
        } else {
            CP_WAIT0();
        }
        __syncthreads();

        uint32_t bufA = sb + (c & 1) * 32768;
        uint32_t bufB = bufA + 16384;
#pragma unroll
        for (int kk = 0; kk < 4; kk++) {
            uint32_t aOff = ((uint32_t)(kk * 32) + aKoff) ^ aSw;
            uint32_t bOff = ((uint32_t)(kk * 32) + bKoff) ^ bSw;
            uint32_t af[4][4], bf[4][2];
#pragma unroll
            for (int mi = 0; mi < 4; mi++)
                LDSM4(af[mi][0], af[mi][1], af[mi][2], af[mi][3],
                      bufA + (uint32_t)((aRow + mi * 16) * 128) + aOff);
#pragma unroll
            for (int j = 0; j < 2; j++) {
                uint32_t r0, r1, r2, r3;
                LDSM4(r0, r1, r2, r3,
                      bufB + (uint32_t)((bRow + j * 16) * 128) + bOff);
                bf[2 * j][0] = r0;     bf[2 * j][1] = r1;
                bf[2 * j + 1][0] = r2; bf[2 * j + 1][1] = r3;
            }
#pragma unroll
            for (int mi = 0; mi < 4; mi++)
#pragma unroll
                for (int ni = 0; ni < 4; ni++)
                    MMA_TF32(acc[mi][ni], af[mi], bf[ni]);
        }
        __syncthreads();
    }

    const int qr = lane >> 2, qc = lane & 3;
#pragma unroll
    for (int mi = 0; mi < 4; mi++) {
        int row = bm * 128 + warp_m * 64 + mi * 16 + qr;
#pragma unroll
        for (int ni = 0; ni < 4; ni++) {
            int col = bn * 128 + warp_n * 32 + ni * 8 + qc * 2;
            float bx = 0.f, by = 0.f;
            if (BIAS) { float2 b2 = *(const float2*)&bias[col]; bx = b2.x; by = b2.y; }
            *(float2*)&Cm[(long)row * N + col] =
                make_float2(acc[mi][ni][0] + bx, acc[mi][ni][1] + by);
            *(float2*)&Cm[(long)(row + 8) * N + col] =
                make_float2(acc[mi][ni][2] + bx, acc[mi][ni][3] + by);
        }
    }
}

// ---------------- weight rounding (Wqkv + Wproj -> tf32) ----------------
__global__ void round_w_kernel(const float* __restrict__ wq, const float* __restrict__ wp) {
    int i = blockIdx.x * blockDim.x + threadIdx.x;
    if (i < 196608) {
        float4 v = ((const float4*)wq)[i];
        ((float4*)g_wq_r)[i] = make_float4(to_tf32(v.x), to_tf32(v.y), to_tf32(v.z), to_tf32(v.w));
    } else {
        float4 v = ((const float4*)wp)[i - 196608];
        ((float4*)g_wp_r)[i - 196608] = make_float4(to_tf32(v.x), to_tf32(v.y), to_tf32(v.z), to_tf32(v.w));
    }
}

// ---------------- prep v2: vectorized avg-pool + window gather ----------------
__global__ void __launch_bounds__(256) prep_kernel(const float* __restrict__ x) {
    int id = blockIdx.x * blockDim.x + threadIdx.x;
    int c4 = (id & 127) << 2;
    int w  = (id >> 7) & 1023;
    int b  = id >> 17;
    int hh = w >> 5, wh = w & 31;

    long r0 = (long)(b * 4096 + (2 * hh) * 64 + 2 * wh) * 512 + c4;
    float4 a00 = *(const float4*)&x[r0];
    float4 a01 = *(const float4*)&x[r0 + 512];
    float4 a10 = *(const float4*)&x[r0 + 64 * 512];
    float4 a11 = *(const float4*)&x[r0 + 65 * 512];

    float4 pool;
    pool.x = to_tf32(0.25f * (a00.x + a01.x + a10.x + a11.x));
    pool.y = to_tf32(0.25f * (a00.y + a01.y + a10.y + a11.y));
    pool.z = to_tf32(0.25f * (a00.z + a01.z + a10.z + a11.z));
    pool.w = to_tf32(0.25f * (a00.w + a01.w + a10.w + a11.w));
    *(float4*)&g_xhi[(long)(b * 1024 + w) * 512 + c4] = pool;

    int t = c4 >> 7;
    int c = (4 * c4) & 511;
    float* wr = &g_win[(long)((b * 1024 + w) * 4 + t) * 512 + c];
    *(float4*)(wr + 0)  = make_float4(to_tf32(a00.x), to_tf32(a01.x), to_tf32(a10.x), to_tf32(a11.x));
    *(float4*)(wr + 4)  = make_float4(to_tf32(a00.y), to_tf32(a01.y), to_tf32(a10.y), to_tf32(a11.y));
    *(float4*)(wr + 8)  = make_float4(to_tf32(a00.z), to_tf32(a01.z), to_tf32(a10.z), to_tf32(a11.z));
    *(float4*)(wr + 12) = make_float4(to_tf32(a00.w), to_tf32(a01.w), to_tf32(a10.w), to_tf32(a11.w));
}

// ======================= flash attention v6 (R11 best: 256 thr, Br=128, no-max) =======================
#define RAWK_OFF 65536
#define RAWV_OFF (65536 + 17408)
#define FLASH_SMEM (65536 + 2 * 17408 + 1024)

__global__ void __launch_bounds__(256, 1) flash_hi_tc() {
    extern __shared__ char fsm[];
    uint32_t sb = (smem_u32(fsm) + 1023u) & ~1023u;
    const uint32_t KH = sb, VS = sb + 16384, PS = sb + 32768;
    const uint32_t RK = sb + RAWK_OFF, RV = sb + RAWV_OFF;

    const int t = threadIdx.x, lane = t & 31, wid = t >> 5;
    const int qt = blockIdx.x, bh = blockIdx.y;
    const int b = bh >> 3, h = bh & 7;

    const int krow = t >> 2, kq4 = t & 3;
    const int vtok = t & 63, vdb = (t >> 6) * 16;
    const uint32_t rkd = RK + (uint32_t)(krow * 272 + kq4 * 64);
    const uint32_t rvd = RV + (uint32_t)(vtok * 272 + vdb * 4);
    const float* kv_base = g_qkv_hi + (long)(b * 1024) * 1536 + 512 + h * 64;

    {
        const float* kg = kv_base + (long)krow * 1536 + kq4 * 16;
        const float* vg = kv_base + (long)vtok * 1536 + 512 + vdb;
#pragma unroll
        for (int i = 0; i < 4; i++) {
            CP_ASYNC16(rkd + i * 16, kg + i * 4);
            CP_ASYNC16(rvd + i * 16, vg + i * 4);
        }
        CP_COMMIT();
    }

    const int l7 = lane & 7, g8 = lane >> 3;
    const int aRow = wid * 16 + (g8 & 1) * 8 + l7;
    const uint32_t aKsel = (uint32_t)((g8 >> 1) * 16);
    const int bRow = (g8 >> 1) * 8 + l7;
    const uint32_t bKsel = (uint32_t)((g8 & 1) * 16);
    const uint32_t swl = (uint32_t)(l7 << 4);
    const uint32_t aBase = (uint32_t)(aRow * 256);
    const int qr = lane >> 2, qc = lane & 3;

    uint32_t qh[8][4];
    {
        int row = t >> 1, hb = t & 1;
        const float* qg = g_qkv_hi + (long)(b * 1024 + qt * 128 + row) * 1536 + h * 64 + hb * 32;
        uint32_t rbase = (uint32_t)(row * 256);
        uint32_t rsw = (uint32_t)((row & 7) << 4);
#pragma unroll
        for (int i = 0; i < 8; i++) {
            float4 v = *(const float4*)(qg + i * 4);
            v.x *= SCALE; v.y *= SCALE; v.z *= SCALE; v.w *= SCALE;
            uint32_t off = ((uint32_t)(hb * 128 + i * 16)) ^ rsw;
            STSV4(KH + rbase + off, to_tf32(v.x), to_tf32(v.y), to_tf32(v.z), to_tf32(v.w));
        }
        __syncthreads();
#pragma unroll
        for (int kk = 0; kk < 8; kk++)
            LDSM4(qh[kk][0], qh[kk][1], qh[kk][2], qh[kk][3],
                  KH + aBase + (((uint32_t)(kk * 32) + aKsel) ^ swl));
    }

    float oacc[8][4];
#pragma unroll
    for (int ni = 0; ni < 8; ni++)
#pragma unroll
        for (int q = 0; q < 4; q++) oacc[ni][q] = 0.f;
    float l0 = 0.f, l1 = 0.f;

    for (int kt = 0; kt < 16; kt++) {
        CP_WAIT0();
        __syncthreads();

        {
            uint32_t rbase = (uint32_t)(krow * 256);
            uint32_t rsw = (uint32_t)((krow & 7) << 4);
#pragma unroll
            for (int i = 0; i < 4; i++) {
                float x_, y_, z_, w_;
                LDSV4(x_, y_, z_, w_, rkd + i * 16);
                uint32_t off = ((uint32_t)(kq4 * 64 + i * 16)) ^ rsw;
                STSV4(KH + rbase + off, to_tf32(x_), to_tf32(y_), to_tf32(z_), to_tf32(w_));
            }
        }
        {
            uint32_t tokb = (uint32_t)(vtok * 4);
#pragma unroll
            for (int i = 0; i < 4; i++) {
                float x_, y_, z_, w_;
                LDSV4(x_, y_, z_, w_, rvd + i * 16);
                int d0 = vdb + i * 4;
                STSB32(VS + (uint32_t)((d0 + 0) * 256) + (tokb ^ (uint32_t)(((d0 + 0) & 7) << 4)), to_tf32(x_));
                STSB32(VS + (uint32_t)((d0 + 1) * 256) + (tokb ^ (uint32_t)(((d0 + 1) & 7) << 4)), to_tf32(y_));
                STSB32(VS + (uint32_t)((d0 + 2) * 256) + (tokb ^ (uint32_t)(((d0 + 2) & 7) << 4)), to_tf32(z_));
                STSB32(VS + (uint32_t)((d0 + 3) * 256) + (tokb ^ (uint32_t)(((d0 + 3) & 7) << 4)), to_tf32(w_));
            }
        }
        if (kt + 1 < 16) {
            const float* kg = kv_base + (long)((kt + 1) * 64 + krow) * 1536 + kq4 * 16;
            const float* vg = kv_base + (long)((kt + 1) * 64 + vtok) * 1536 + 512 + vdb;
#pragma unroll
            for (int i = 0; i < 4; i++) {
                CP_ASYNC16(rkd + i * 16, kg + i * 4);
                CP_ASYNC16(rvd + i * 16, vg + i * 4);
            }
            CP_COMMIT();
        }
        __syncthreads();

        float sacc[8][4];
#pragma unroll
        for (int ni = 0; ni < 8; ni++)
#pragma unroll
            for (int q = 0; q < 4; q++) sacc[ni][q] = 0.f;

#pragma unroll
        for (int kk = 0; kk < 8; kk++) {
            uint32_t bOff = ((uint32_t)(kk * 32) + bKsel) ^ swl;
#pragma unroll
            for (int j = 0; j < 4; j++) {
                uint32_t r0, r1, r2, r3;
                LDSM4(r0, r1, r2, r3, KH + (uint32_t)((bRow + j * 16) * 256) + bOff);
                uint32_t bh0[2] = {r0, r1}, bh1[2] = {r2, r3};
                MMA_TF32(sacc[2 * j],     qh[kk], bh0);
                MMA_TF32(sacc[2 * j + 1], qh[kk], bh1);
            }
        }

        float rs0 = 0.f, rs1 = 0.f;
        const uint32_t pr0 = PS + (uint32_t)((wid * 16 + qr) * 256);
        const uint32_t pr1 = PS + (uint32_t)((wid * 16 + qr + 8) * 256);
        const uint32_t sw0 = (uint32_t)((qr & 7) << 4);
        const uint32_t sw1 = (uint32_t)(((qr + 8) & 7) << 4);
#pragma unroll
        for (int ni = 0; ni < 8; ni++) {
            float q0 = to_tf32(__expf(sacc[ni][0]));
            float q1 = to_tf32(__expf(sacc[ni][1]));
            float q2 = to_tf32(__expf(sacc[ni][2]));
            float q3 = to_tf32(__expf(sacc[ni][3]));
            rs0 += q0 + q1; rs1 += q2 + q3;
            uint32_t cb = (uint32_t)(ni * 32 + qc * 8);
            STSV2(pr0 + (cb ^ sw0), q0, q1);
            STSV2(pr1 + (cb ^ sw1), q2, q3);
        }
        rs0 += __shfl_xor_sync(0xffffffffu, rs0, 1);
        rs0 += __shfl_xor_sync(0xffffffffu, rs0, 2);
        rs1 += __shfl_xor_sync(0xffffffffu, rs1, 1);
        rs1 += __shfl_xor_sync(0xffffffffu, rs1, 2);
        l0 += rs0; l1 += rs1;
        __syncwarp();

#pragma unroll
        for (int kk = 0; kk < 8; kk++) {
            uint32_t kb = (uint32_t)(kk * 32);
            uint32_t ap[4];
            LDSM4(ap[0], ap[1], ap[2], ap[3], PS + aBase + ((kb + aKsel) ^ swl));
            uint32_t bOff = (kb + bKsel) ^ swl;
#pragma unroll
            for (int j = 0; j < 4; j++) {
                uint32_t r0, r1, r2, r3;
                LDSM4(r0, r1, r2, r3, VS + (uint32_t)((bRow + j * 16) * 256) + bOff);
                uint32_t bv0[2] = {r0, r1}, bv1[2] = {r2, r3};
                MMA_TF32(oacc[2 * j],     ap, bv0);
                MMA_TF32(oacc[2 * j + 1], ap, bv1);
            }
        }
    }

    float inv0 = 1.f / l0, inv1 = 1.f / l1;
    long r0g = (long)(b * 1024 + qt * 128 + wid * 16 + qr) * 512 + h * 64;
    long r1g = r0g + 8 * 512;
#pragma unroll
    for (int ni = 0; ni < 8; ni++) {
        int col = ni * 8 + qc * 2;
        *(float2*)&g_out_hi[r0g + col] = make_float2(oacc[ni][0] * inv0, oacc[ni][1] * inv0);
        *(float2*)&g_out_hi[r1g + col] = make_float2(oacc[ni][2] * inv1, oacc[ni][3] * inv1);
    }
}

// ---------------- lo-branch windowed attention ONLY (unrounded out_lo -> g_comb) ----------------
// No smem, ~40 regs: co-resides with flash on the same SMs.
__global__ void __launch_bounds__(256) lo_attn_only_kernel() {
    int gid  = blockIdx.x * blockDim.x + threadIdx.x;
    int warp = gid >> 5;
    int lane = gid & 31;
    int h = warp & 7;
    int w = (warp >> 3) & 1023;
    int b = warp >> 13;

    const float* base = g_qkv_lo + (long)((b * 1024 + w) * 4) * 1536 + h * 64 + 2 * lane;
    float2 q[4], k[4], v[4];
#pragma unroll
    for (int t = 0; t < 4; t++) {
        q[t] = *(const float2*)(base + (long)t * 1536);
        k[t] = *(const float2*)(base + (long)t * 1536 + 512);
        v[t] = *(const float2*)(base + (long)t * 1536 + 1024);
    }

    float lg[4][4];
#pragma unroll
    for (int ti = 0; ti < 4; ti++)
#pragma unroll
        for (int tj = 0; tj < 4; tj++) {
            float p = q[ti].x * k[tj].x + q[ti].y * k[tj].y;
            p += __shfl_xor_sync(0xffffffffu, p, 16);
            p += __shfl_xor_sync(0xffffffffu, p, 8);
            p += __shfl_xor_sync(0xffffffffu, p, 4);
            p += __shfl_xor_sync(0xffffffffu, p, 2);
            p += __shfl_xor_sync(0xffffffffu, p, 1);
            lg[ti][tj] = p * SCALE;
        }

    int hh = w >> 5, wh = w & 31;
    int ccol = h * 64 + 2 * lane;
#pragma unroll
    for (int ti = 0; ti < 4; ti++) {
        float mx = fmaxf(fmaxf(lg[ti][0], lg[ti][1]), fmaxf(lg[ti][2], lg[ti][3]));
        float e0 = __expf(lg[ti][0] - mx);
        float e1 = __expf(lg[ti][1] - mx);
        float e2 = __expf(lg[ti][2] - mx);
        float e3 = __expf(lg[ti][3] - mx);
        float is = 1.f / (e0 + e1 + e2 + e3);
        float ox = (e0 * v[0].x + e1 * v[1].x + e2 * v[2].x + e3 * v[3].x) * is;
        float oy = (e0 * v[0].y + e1 * v[1].y + e2 * v[2].y + e3 * v[3].y) * is;

        int pos = (2 * hh + (ti >> 1)) * 64 + 2 * wh + (ti & 1);
        *(float2*)&g_comb[(long)(b * 4096 + pos) * 512 + ccol] = make_float2(ox, oy);
    }
}

// ---------------- bilinear upsample 32->64 + add (final tf32 round) ----------------
__global__ void __launch_bounds__(128) upsample_add_kernel() {
    int blk = blockIdx.x;           // 32768 = B * 4096
    int b = blk >> 12;
    int p = blk & 4095;
    int y = p >> 6, xq = p & 63;

    float sy = 0.5f * y - 0.25f;
    int   y0 = (int)floorf(sy);
    float fy = sy - (float)y0;
    int   y1 = min(y0 + 1, 31); y0 = max(y0, 0);

    float sx = 0.5f * xq - 0.25f;
    int   x0 = (int)floorf(sx);
    float fx = sx - (float)x0;
    int   x1 = min(x0 + 1, 31); x0 = max(x0, 0);

    float w00 = (1.f - fy) * (1.f - fx), w01 = (1.f - fy) * fx;
    float w10 = fy * (1.f - fx),         w11 = fy * fx;

    int c = threadIdx.x * 4;
    long base = (long)b * 1024 * 512;
    float4 v00 = *(const float4*)&g_out_hi[base + (long)(y0 * 32 + x0) * 512 + c];
    float4 v01 = *(const float4*)&g_out_hi[base + (long)(y0 * 32 + x1) * 512 + c];
    float4 v10 = *(const float4*)&g_out_hi[base + (long)(y1 * 32 + x0) * 512 + c];
    float4 v11 = *(const float4*)&g_out_hi[base + (long)(y1 * 32 + x1) * 512 + c];

    float4* dst = (float4*)&g_comb[(long)(b * 4096 + p) * 512 + c];
    float4 d = *dst;
    d.x = to_tf32(d.x + w00 * v00.x + w01 * v01.x + w10 * v10.x + w11 * v11.x);
    d.y = to_tf32(d.y + w00 * v00.y + w01 * v01.y + w10 * v10.y + w11 * v11.y);
    d.z = to_tf32(d.z + w00 * v00.z + w01 * v01.z + w10 * v10.z + w11 * v11.z);
    d.w = to_tf32(d.w + w00 * v00.w + w01 * v01.w + w10 * v10.w + w11 * v11.w);
    *dst = d;
}

// ---------------- launch (dual-stream: lo-GEMM + lo_attn on s2, overlap flash) ----------------
extern "C" void kernel_launch(void* const* d_in, const int* in_sizes, int n_in,
                              void* d_out, int out_size) {
    const float* x     = (const float*)d_in[0];
    const float* Wqkv  = (const float*)d_in[1];
    const float* Wproj = (const float*)d_in[2];
    const float* bproj = (const float*)d_in[3];
    float* out = (float*)d_out;

    float *xhi, *qkvhi, *win, *qkvlo, *comb, *wqr, *wpr;
    cudaGetSymbolAddress((void**)&xhi,   g_xhi);
    cudaGetSymbolAddress((void**)&qkvhi, g_qkv_hi);
    cudaGetSymbolAddress((void**)&win,   g_win);
    cudaGetSymbolAddress((void**)&qkvlo, g_qkv_lo);
    cudaGetSymbolAddress((void**)&comb,  g_comb);
    cudaGetSymbolAddress((void**)&wqr,   g_wq_r);
    cudaGetSymbolAddress((void**)&wpr,   g_wp_r);

    cudaFuncSetAttribute(mma_gemm<false>, cudaFuncAttributeMaxDynamicSharedMemorySize, GEMM_SMEM);
    cudaFuncSetAttribute(mma_gemm<true>,  cudaFuncAttributeMaxDynamicSharedMemorySize, GEMM_SMEM);
    cudaFuncSetAttribute(flash_hi_tc,     cudaFuncAttributeMaxDynamicSharedMemorySize, FLASH_SMEM);

    static cudaStream_t s2 = nullptr;
    static cudaEvent_t evFork = nullptr, evJoin = nullptr;
    if (s2 == nullptr) {
        cudaStreamCreateWithFlags(&s2, cudaStreamNonBlocking);
        cudaEventCreateWithFlags(&evFork, cudaEventDisableTiming);
        cudaEventCreateWithFlags(&evJoin, cudaEventDisableTiming);
    }

    // 0. weight rounding + prep (main stream)
    round_w_kernel<<<1024, 256>>>(Wqkv, Wproj);
    prep_kernel<<<4096, 256>>>(x);

    // fork: lo QKV GEMM then lo attention on side stream (lo_attn co-resides with flash)
    cudaEventRecord(evFork, 0);
    cudaStreamWaitEvent(s2, evFork, 0);
    mma_gemm<false><<<dim3(12, 256), 256, GEMM_SMEM, s2>>>(win, wqr, nullptr, qkvlo, 32768, 1536, 512);
    lo_attn_only_kernel<<<8192, 256, 0, s2>>>();
    cudaEventRecord(evJoin, s2);

    // main stream: hi QKV GEMM -> flash attention
    mma_gemm<false><<<dim3(12, 64), 256, GEMM_SMEM>>>(xhi, wqr, nullptr, qkvhi, 8192, 1536, 512);
    flash_hi_tc<<<dim3(8, 64), 256, FLASH_SMEM>>>();

    // join, then upsample-add (needs out_hi + comb) and output projection
    cudaStreamWaitEvent(0, evJoin, 0);
    upsample_add_kernel<<<32768, 128>>>();
    mma_gemm<true><<<dim3(4, 256), 256, GEMM_SMEM>>>(comb, wpr, bproj, out, 32768, 512, 512);
}

// round 14
// speedup vs baseline: 1.1068x; 1.0161x over previous
#include <cuda_runtime.h>
#include <math.h>
#include <stdint.h>

// ---------------- problem constants ----------------
#define B_    8
#define N_    4096      // tokens per batch (64x64)
#define C_    512
#define NH_   8         // heads
#define HD_   64        // head dim
#define SCALE 0.125f    // hd^-0.5

// ---------------- scratch (device globals; no allocation allowed) ----------------
__device__ float g_xhi   [B_*1024*C_];     //  16 MB  pooled tokens (tf32-rounded)
__device__ float g_qkv_hi[B_*1024*3*C_];   //  50 MB
__device__ float g_out_hi[B_*1024*C_];     //  16 MB
__device__ float g_win   [B_*N_*C_];       //  64 MB  window tokens (tf32-rounded)
__device__ float g_qkv_lo[B_*N_*3*C_];     // 201 MB
__device__ float g_comb  [B_*N_*C_];       //  64 MB  out_lo, then out_lo+hi (tf32)
__device__ float g_wq_r  [3*C_*C_];        //   3 MB  Wqkv tf32-rounded
__device__ float g_wp_r  [C_*C_];          //   1 MB  Wproj tf32-rounded

// ======================= PTX helpers =======================
__device__ __forceinline__ uint32_t smem_u32(const void* p) {
    uint32_t a;
    asm("{ .reg .u64 t; cvta.to.shared.u64 t, %1; cvt.u32.u64 %0, t; }" : "=r"(a) : "l"(p));
    return a;
}
__device__ __forceinline__ float to_tf32(float x) {
    float r;
    asm("cvt.rna.tf32.f32 %0, %1;" : "=f"(r) : "f"(x));
    return r;
}

#define LDSM4(d0, d1, d2, d3, addr)                                            \
    asm volatile("ldmatrix.sync.aligned.m8n8.x4.shared.b16 {%0,%1,%2,%3}, [%4];" \
                 : "=r"(d0), "=r"(d1), "=r"(d2), "=r"(d3) : "r"(addr))

#define MMA_TF32(c, a, b)                                                      \
    asm volatile("mma.sync.aligned.m16n8k8.row.col.f32.tf32.tf32.f32 "         \
                 "{%0,%1,%2,%3}, {%4,%5,%6,%7}, {%8,%9}, {%0,%1,%2,%3};"       \
                 : "+f"((c)[0]), "+f"((c)[1]), "+f"((c)[2]), "+f"((c)[3])      \
                 : "r"((a)[0]), "r"((a)[1]), "r"((a)[2]), "r"((a)[3]),         \
                   "r"((b)[0]), "r"((b)[1]))

#define STSV4(addr, x, y, z, w)                                                \
    asm volatile("st.shared.v4.b32 [%0], {%1,%2,%3,%4};"                       \
                 :: "r"(addr), "f"(x), "f"(y), "f"(z), "f"(w) : "memory")
#define STSV2(addr, x, y)                                                      \
    asm volatile("st.shared.v2.b32 [%0], {%1,%2};"                             \
                 :: "r"(addr), "f"(x), "f"(y) : "memory")
#define STSB32(addr, x)                                                        \
    asm volatile("st.shared.b32 [%0], %1;" :: "r"(addr), "f"(x) : "memory")
#define LDSV4(x, y, z, w, addr)                                                \
    asm volatile("ld.shared.v4.b32 {%0,%1,%2,%3}, [%4];"                       \
                 : "=f"(x), "=f"(y), "=f"(z), "=f"(w) : "r"(addr))
#define CP_ASYNC16(dst, src)                                                   \
    asm volatile("cp.async.cg.shared.global [%0], [%1], 16;"                   \
                 :: "r"(dst), "l"(src) : "memory")
#define CP_COMMIT()  asm volatile("cp.async.commit_group;" ::: "memory")
#define CP_WAIT0()   asm volatile("cp.async.wait_group 0;" ::: "memory")
#define CP_WAIT1()   asm volatile("cp.async.wait_group 1;" ::: "memory")

// ======================= mma.sync tf32 GEMM v3: 3-stage ring, 1 barrier/chunk =======================
// C[M,N] = A[M,K] * B[N,K]^T (+bias). Inputs pre-rounded to tf32.
// Tile 128x128, BK=32; stages of 32KB (A 16K + B 16K); 2 blocks/SM.
#define GEMM_SMEM (1024 + 3 * 32768)

template <bool BIAS>
__global__ void __launch_bounds__(256, 2) mma_gemm(
    const float* __restrict__ A, const float* __restrict__ Bm,
    const float* __restrict__ bias, float* __restrict__ Cm,
    int M, int N, int K)
{
    extern __shared__ char dsm[];
    uint32_t sb = (smem_u32(dsm) + 1023u) & ~1023u;

    const int t = threadIdx.x;
    const int bm = blockIdx.y, bn = blockIdx.x;
    const int lane = t & 31, wid = t >> 5;
    const int warp_m = wid & 1, warp_n = wid >> 1;

    const int f4 = t & 7;
    const int row0 = t >> 3;
    const float* Ap = A  + (long)(bm * 128 + row0) * K + f4 * 4;
    const float* Bp = Bm + (long)(bn * 128 + row0) * K + f4 * 4;
    uint32_t stOff[4];
#pragma unroll
    for (int g = 0; g < 4; g++) {
        uint32_t off = (row0 + 32 * g) * 128 + f4 * 16;
        stOff[g] = off ^ ((off >> 3) & 0x70);
    }

    const int l = lane & 7, g8 = lane >> 3;
    const int aRow = warp_m * 64 + (g8 & 1) * 8 + l;
    const uint32_t aSw   = (uint32_t)((aRow & 7) << 4);
    const uint32_t aKoff = (uint32_t)((g8 >> 1) * 16);
    const int bRow = warp_n * 32 + (g8 >> 1) * 8 + l;
    const uint32_t bSw   = (uint32_t)((bRow & 7) << 4);
    const uint32_t bKoff = (uint32_t)((g8 & 1) * 16);

    float acc[4][4][4];
#pragma unroll
    for (int mi = 0; mi < 4; mi++)
#pragma unroll
        for (int ni = 0; ni < 4; ni++)
#pragma unroll
            for (int q = 0; q < 4; q++) acc[mi][ni][q] = 0.f;

    const int KC = K >> 5;   // >= 16 in all our calls

    // prologue: issue chunks 0 and 1 into stages 0,1
#pragma unroll
    for (int s = 0; s < 2; s++) {
        uint32_t sA = sb + (uint32_t)s * 32768u, sB = sA + 16384;
        const float* An = Ap + s * 32;
        const float* Bn = Bp + s * 32;
#pragma unroll
        for (int g = 0; g < 4; g++) {
            CP_ASYNC16(sA + stOff[g], An + (long)(g * 32) * K);
            CP_ASYNC16(sB + stOff[g], Bn + (long)(g * 32) * K);
        }
        CP_COMMIT();
    }

    int stage = 0;
    for (int c = 0; c < KC; c++) {
        if (c + 1 < KC) { CP_WAIT1(); } else { CP_WAIT0(); }
        __syncthreads();   // chunk c visible; all warps done reading stage (c-1)%3

        uint32_t bufA = sb + (uint32_t)stage * 32768u;
        uint32_t bufB = bufA + 16384;
#pragma unroll
        for (int kk = 0; kk < 4; kk++) {
            uint32_t aOff = ((uint32_t)(kk * 32) + aKoff) ^ aSw;
            uint32_t bOff = ((uint32_t)(kk * 32) + bKoff) ^ bSw;
            uint32_t af[4][4], bf[4][2];
#pragma unroll
            for (int mi = 0; mi < 4; mi++)
                LDSM4(af[mi][0], af[mi][1], af[mi][2], af[mi][3],
                      bufA + (uint32_t)((aRow + mi * 16) * 128) + aOff);
#pragma unroll
            for (int j = 0; j < 2; j++) {
                uint32_t r0, r1, r2, r3;
                LDSM4(r0, r1, r2, r3,
                      bufB + (uint32_t)((bRow + j * 16) * 128) + bOff);
                bf[2 * j][0] = r0;     bf[2 * j][1] = r1;
                bf[2 * j + 1][0] = r2; bf[2 * j + 1][1] = r3;
            }
#pragma unroll
            for (int mi = 0; mi < 4; mi++)
#pragma unroll
                for (int ni = 0; ni < 4; ni++)
                    MMA_TF32(acc[mi][ni], af[mi], bf[ni]);
        }

        // issue chunk c+2 into stage (c+2)%3 (post-barrier: its last readers were iter c-1)
        if (c + 2 < KC) {
            int ns = stage + 2; if (ns >= 3) ns -= 3;
            uint32_t sA = sb + (uint32_t)ns * 32768u, sB = sA + 16384;
            const float* An = Ap + (c + 2) * 32;
            const float* Bn = Bp + (c + 2) * 32;
#pragma unroll
            for (int g = 0; g < 4; g++) {
                CP_ASYNC16(sA + stOff[g], An + (long)(g * 32) * K);
                CP_ASYNC16(sB + stOff[g], Bn + (long)(g * 32) * K);
            }
            CP_COMMIT();
        }
        if (++stage == 3) stage = 0;
    }

    const int qr = lane >> 2, qc = lane & 3;
#pragma unroll
    for (int mi = 0; mi < 4; mi++) {
        int row = bm * 128 + warp_m * 64 + mi * 16 + qr;
#pragma unroll
        for (int ni = 0; ni < 4; ni++) {
            int col = bn * 128 + warp_n * 32 + ni * 8 + qc * 2;
            float bx = 0.f, by = 0.f;
            if (BIAS) { float2 b2 = *(const float2*)&bias[col]; bx = b2.x; by = b2.y; }
            *(float2*)&Cm[(long)row * N + col] =
                make_float2(acc[mi][ni][0] + bx, acc[mi][ni][1] + by);
            *(float2*)&Cm[(long)(row + 8) * N + col] =
                make_float2(acc[mi][ni][2] + bx, acc[mi][ni][3] + by);
        }
    }
}

// ---------------- weight rounding (Wqkv + Wproj -> tf32) ----------------
__global__ void round_w_kernel(const float* __restrict__ wq, const float* __restrict__ wp) {
    int i = blockIdx.x * blockDim.x + threadIdx.x;
    if (i < 196608) {
        float4 v = ((const float4*)wq)[i];
        ((float4*)g_wq_r)[i] = make_float4(to_tf32(v.x), to_tf32(v.y), to_tf32(v.z), to_tf32(v.w));
    } else {
        float4 v = ((const float4*)wp)[i - 196608];
        ((float4*)g_wp_r)[i - 196608] = make_float4(to_tf32(v.x), to_tf32(v.y), to_tf32(v.z), to_tf32(v.w));
    }
}

// ---------------- prep v2: vectorized avg-pool + window gather ----------------
__global__ void __launch_bounds__(256) prep_kernel(const float* __restrict__ x) {
    int id = blockIdx.x * blockDim.x + threadIdx.x;
    int c4 = (id & 127) << 2;
    int w  = (id >> 7) & 1023;
    int b  = id >> 17;
    int hh = w >> 5, wh = w & 31;

    long r0 = (long)(b * 4096 + (2 * hh) * 64 + 2 * wh) * 512 + c4;
    float4 a00 = *(const float4*)&x[r0];
    float4 a01 = *(const float4*)&x[r0 + 512];
    float4 a10 = *(const float4*)&x[r0 + 64 * 512];
    float4 a11 = *(const float4*)&x[r0 + 65 * 512];

    float4 pool;
    pool.x = to_tf32(0.25f * (a00.x + a01.x + a10.x + a11.x));
    pool.y = to_tf32(0.25f * (a00.y + a01.y + a10.y + a11.y));
    pool.z = to_tf32(0.25f * (a00.z + a01.z + a10.z + a11.z));
    pool.w = to_tf32(0.25f * (a00.w + a01.w + a10.w + a11.w));
    *(float4*)&g_xhi[(long)(b * 1024 + w) * 512 + c4] = pool;

    int t = c4 >> 7;
    int c = (4 * c4) & 511;
    float* wr = &g_win[(long)((b * 1024 + w) * 4 + t) * 512 + c];
    *(float4*)(wr + 0)  = make_float4(to_tf32(a00.x), to_tf32(a01.x), to_tf32(a10.x), to_tf32(a11.x));
    *(float4*)(wr + 4)  = make_float4(to_tf32(a00.y), to_tf32(a01.y), to_tf32(a10.y), to_tf32(a11.y));
    *(float4*)(wr + 8)  = make_float4(to_tf32(a00.z), to_tf32(a01.z), to_tf32(a10.z), to_tf32(a11.z));
    *(float4*)(wr + 12) = make_float4(to_tf32(a00.w), to_tf32(a01.w), to_tf32(a10.w), to_tf32(a11.w));
}

// ======================= flash attention v6 (256 thr, Br=128, no-max) =======================
#define RAWK_OFF 65536
#define RAWV_OFF (65536 + 17408)
#define FLASH_SMEM (65536 + 2 * 17408 + 1024)

__global__ void __launch_bounds__(256, 1) flash_hi_tc() {
    extern __shared__ char fsm[];
    uint32_t sb = (smem_u32(fsm) + 1023u) & ~1023u;
    const uint32_t KH = sb, VS = sb + 16384, PS = sb + 32768;
    const uint32_t RK = sb + RAWK_OFF, RV = sb + RAWV_OFF;

    const int t = threadIdx.x, lane = t & 31, wid = t >> 5;
    const int qt = blockIdx.x, bh = blockIdx.y;
    const int b = bh >> 3, h = bh & 7;

    const int krow = t >> 2, kq4 = t & 3;
    const int vtok = t & 63, vdb = (t >> 6) * 16;
    const uint32_t rkd = RK + (uint32_t)(krow * 272 + kq4 * 64);
    const uint32_t rvd = RV + (uint32_t)(vtok * 272 + vdb * 4);
    const float* kv_base = g_qkv_hi + (long)(b * 1024) * 1536 + 512 + h * 64;

    {
        const float* kg = kv_base + (long)krow * 1536 + kq4 * 16;
        const float* vg = kv_base + (long)vtok * 1536 + 512 + vdb;
#pragma unroll
        for (int i = 0; i < 4; i++) {
            CP_ASYNC16(rkd + i * 16, kg + i * 4);
            CP_ASYNC16(rvd + i * 16, vg + i * 4);
        }
        CP_COMMIT();
    }

    const int l7 = lane & 7, g8 = lane >> 3;
    const int aRow = wid * 16 + (g8 & 1) * 8 + l7;
    const uint32_t aKsel = (uint32_t)((g8 >> 1) * 16);
    const int bRow = (g8 >> 1) * 8 + l7;
    const uint32_t bKsel = (uint32_t)((g8 & 1) * 16);
    const uint32_t swl = (uint32_t)(l7 << 4);
    const uint32_t aBase = (uint32_t)(aRow * 256);
    const int qr = lane >> 2, qc = lane & 3;

    uint32_t qh[8][4];
    {
        int row = t >> 1, hb = t & 1;
        const float* qg = g_qkv_hi + (long)(b * 1024 + qt * 128 + row) * 1536 + h * 64 + hb * 32;
        uint32_t rbase = (uint32_t)(row * 256);
        uint32_t rsw = (uint32_t)((row & 7) << 4);
#pragma unroll
        for (int i = 0; i < 8; i++) {
            float4 v = *(const float4*)(qg + i * 4);
            v.x *= SCALE; v.y *= SCALE; v.z *= SCALE; v.w *= SCALE;
            uint32_t off = ((uint32_t)(hb * 128 + i * 16)) ^ rsw;
            STSV4(KH + rbase + off, to_tf32(v.x), to_tf32(v.y), to_tf32(v.z), to_tf32(v.w));
        }
        __syncthreads();
#pragma unroll
        for (int kk = 0; kk < 8; kk++)
            LDSM4(qh[kk][0], qh[kk][1], qh[kk][2], qh[kk][3],
                  KH + aBase + (((uint32_t)(kk * 32) + aKsel) ^ swl));
    }

    float oacc[8][4];
#pragma unroll
    for (int ni = 0; ni < 8; ni++)
#pragma unroll
        for (int q = 0; q < 4; q++) oacc[ni][q] = 0.f;
    float l0 = 0.f, l1 = 0.f;

    for (int kt = 0; kt < 16; kt++) {
        CP_WAIT0();
        __syncthreads();

        {
            uint32_t rbase = (uint32_t)(krow * 256);
            uint32_t rsw = (uint32_t)((krow & 7) << 4);
#pragma unroll
            for (int i = 0; i < 4; i++) {
                float x_, y_, z_, w_;
                LDSV4(x_, y_, z_, w_, rkd + i * 16);
                uint32_t off = ((uint32_t)(kq4 * 64 + i * 16)) ^ rsw;
                STSV4(KH + rbase + off, to_tf32(x_), to_tf32(y_), to_tf32(z_), to_tf32(w_));
            }
        }
        {
            uint32_t tokb = (uint32_t)(vtok * 4);
#pragma unroll
            for (int i = 0; i < 4; i++) {
                float x_, y_, z_, w_;
                LDSV4(x_, y_, z_, w_, rvd + i * 16);
                int d0 = vdb + i * 4;
                STSB32(VS + (uint32_t)((d0 + 0) * 256) + (tokb ^ (uint32_t)(((d0 + 0) & 7) << 4)), to_tf32(x_));
                STSB32(VS + (uint32_t)((d0 + 1) * 256) + (tokb ^ (uint32_t)(((d0 + 1) & 7) << 4)), to_tf32(y_));
                STSB32(VS + (uint32_t)((d0 + 2) * 256) + (tokb ^ (uint32_t)(((d0 + 2) & 7) << 4)), to_tf32(z_));
                STSB32(VS + (uint32_t)((d0 + 3) * 256) + (tokb ^ (uint32_t)(((d0 + 3) & 7) << 4)), to_tf32(w_));
            }
        }
        if (kt + 1 < 16) {
            const float* kg = kv_base + (long)((kt + 1) * 64 + krow) * 1536 + kq4 * 16;
            const float* vg = kv_base + (long)((kt + 1) * 64 + vtok) * 1536 + 512 + vdb;
#pragma unroll
            for (int i = 0; i < 4; i++) {
                CP_ASYNC16(rkd + i * 16, kg + i * 4);
                CP_ASYNC16(rvd + i * 16, vg + i * 4);
            }
            CP_COMMIT();
        }
        __syncthreads();

        float sacc[8][4];
#pragma unroll
        for (int ni = 0; ni < 8; ni++)
#pragma unroll
            for (int q = 0; q < 4; q++) sacc[ni][q] = 0.f;

#pragma unroll
        for (int kk = 0; kk < 8; kk++) {
            uint32_t bOff = ((uint32_t)(kk * 32) + bKsel) ^ swl;
#pragma unroll
            for (int j = 0; j < 4; j++) {
                uint32_t r0, r1, r2, r3;
                LDSM4(r0, r1, r2, r3, KH + (uint32_t)((bRow + j * 16) * 256) + bOff);
                uint32_t bh0[2] = {r0, r1}, bh1[2] = {r2, r3};
                MMA_TF32(sacc[2 * j],     qh[kk], bh0);
                MMA_TF32(sacc[2 * j + 1], qh[kk], bh1);
            }
        }

        float rs0 = 0.f, rs1 = 0.f;
        const uint32_t pr0 = PS + (uint32_t)((wid * 16 + qr) * 256);
        const uint32_t pr1 = PS + (uint32_t)((wid * 16 + qr + 8) * 256);
        const uint32_t sw0 = (uint32_t)((qr & 7) << 4);
        const uint32_t sw1 = (uint32_t)(((qr + 8) & 7) << 4);
#pragma unroll
        for (int ni = 0; ni < 8; ni++) {
            float q0 = to_tf32(__expf(sacc[ni][0]));
            float q1 = to_tf32(__expf(sacc[ni][1]));
            float q2 = to_tf32(__expf(sacc[ni][2]));
            float q3 = to_tf32(__expf(sacc[ni][3]));
            rs0 += q0 + q1; rs1 += q2 + q3;
            uint32_t cb = (uint32_t)(ni * 32 + qc * 8);
            STSV2(pr0 + (cb ^ sw0), q0, q1);
            STSV2(pr1 + (cb ^ sw1), q2, q3);
        }
        rs0 += __shfl_xor_sync(0xffffffffu, rs0, 1);
        rs0 += __shfl_xor_sync(0xffffffffu, rs0, 2);
        rs1 += __shfl_xor_sync(0xffffffffu, rs1, 1);
        rs1 += __shfl_xor_sync(0xffffffffu, rs1, 2);
        l0 += rs0; l1 += rs1;
        __syncwarp();

#pragma unroll
        for (int kk = 0; kk < 8; kk++) {
            uint32_t kb = (uint32_t)(kk * 32);
            uint32_t ap[4];
            LDSM4(ap[0], ap[1], ap[2], ap[3], PS + aBase + ((kb + aKsel) ^ swl));
            uint32_t bOff = (kb + bKsel) ^ swl;
#pragma unroll
            for (int j = 0; j < 4; j++) {
                uint32_t r0, r1, r2, r3;
                LDSM4(r0, r1, r2, r3, VS + (uint32_t)((bRow + j * 16) * 256) + bOff);
                uint32_t bv0[2] = {r0, r1}, bv1[2] = {r2, r3};
                MMA_TF32(oacc[2 * j],     ap, bv0);
                MMA_TF32(oacc[2 * j + 1], ap, bv1);
            }
        }
    }

    float inv0 = 1.f / l0, inv1 = 1.f / l1;
    long r0g = (long)(b * 1024 + qt * 128 + wid * 16 + qr) * 512 + h * 64;
    long r1g = r0g + 8 * 512;
#pragma unroll
    for (int ni = 0; ni < 8; ni++) {
        int col = ni * 8 + qc * 2;
        *(float2*)&g_out_hi[r0g + col] = make_float2(oacc[ni][0] * inv0, oacc[ni][1] * inv0);
        *(float2*)&g_out_hi[r1g + col] = make_float2(oacc[ni][2] * inv1, oacc[ni][3] * inv1);
    }
}

// ---------------- lo-branch windowed attention ONLY (unrounded out_lo -> g_comb) ----------------
__global__ void __launch_bounds__(256) lo_attn_only_kernel() {
    int gid  = blockIdx.x * blockDim.x + threadIdx.x;
    int warp = gid >> 5;
    int lane = gid & 31;
    int h = warp & 7;
    int w = (warp >> 3) & 1023;
    int b = warp >> 13;

    const float* base = g_qkv_lo + (long)((b * 1024 + w) * 4) * 1536 + h * 64 + 2 * lane;
    float2 q[4], k[4], v[4];
#pragma unroll
    for (int t = 0; t < 4; t++) {
        q[t] = *(const float2*)(base + (long)t * 1536);
        k[t] = *(const float2*)(base + (long)t * 1536 + 512);
        v[t] = *(const float2*)(base + (long)t * 1536 + 1024);
    }

    float lg[4][4];
#pragma unroll
    for (int ti = 0; ti < 4; ti++)
#pragma unroll
        for (int tj = 0; tj < 4; tj++) {
            float p = q[ti].x * k[tj].x + q[ti].y * k[tj].y;
            p += __shfl_xor_sync(0xffffffffu, p, 16);
            p += __shfl_xor_sync(0xffffffffu, p, 8);
            p += __shfl_xor_sync(0xffffffffu, p, 4);
            p += __shfl_xor_sync(0xffffffffu, p, 2);
            p += __shfl_xor_sync(0xffffffffu, p, 1);
            lg[ti][tj] = p * SCALE;
        }

    int hh = w >> 5, wh = w & 31;
    int ccol = h * 64 + 2 * lane;
#pragma unroll
    for (int ti = 0; ti < 4; ti++) {
        float mx = fmaxf(fmaxf(lg[ti][0], lg[ti][1]), fmaxf(lg[ti][2], lg[ti][3]));
        float e0 = __expf(lg[ti][0] - mx);
        float e1 = __expf(lg[ti][1] - mx);
        float e2 = __expf(lg[ti][2] - mx);
        float e3 = __expf(lg[ti][3] - mx);
        float is = 1.f / (e0 + e1 + e2 + e3);
        float ox = (e0 * v[0].x + e1 * v[1].x + e2 * v[2].x + e3 * v[3].x) * is;
        float oy = (e0 * v[0].y + e1 * v[1].y + e2 * v[2].y + e3 * v[3].y) * is;

        int pos = (2 * hh + (ti >> 1)) * 64 + 2 * wh + (ti & 1);
        *(float2*)&g_comb[(long)(b * 4096 + pos) * 512 + ccol] = make_float2(ox, oy);
    }
}

// ---------------- bilinear upsample 32->64 + add (final tf32 round) ----------------
__global__ void __launch_bounds__(128) upsample_add_kernel() {
    int blk = blockIdx.x;
    int b = blk >> 12;
    int p = blk & 4095;
    int y = p >> 6, xq = p & 63;

    float sy = 0.5f * y - 0.25f;
    int   y0 = (int)floorf(sy);
    float fy = sy - (float)y0;
    int   y1 = min(y0 + 1, 31); y0 = max(y0, 0);

    float sx = 0.5f * xq - 0.25f;
    int   x0 = (int)floorf(sx);
    float fx = sx - (float)x0;
    int   x1 = min(x0 + 1, 31); x0 = max(x0, 0);

    float w00 = (1.f - fy) * (1.f - fx), w01 = (1.f - fy) * fx;
    float w10 = fy * (1.f - fx),         w11 = fy * fx;

    int c = threadIdx.x * 4;
    long base = (long)b * 1024 * 512;
    float4 v00 = *(const float4*)&g_out_hi[base + (long)(y0 * 32 + x0) * 512 + c];
    float4 v01 = *(const float4*)&g_out_hi[base + (long)(y0 * 32 + x1) * 512 + c];
    float4 v10 = *(const float4*)&g_out_hi[base + (long)(y1 * 32 + x0) * 512 + c];
    float4 v11 = *(const float4*)&g_out_hi[base + (long)(y1 * 32 + x1) * 512 + c];

    float4* dst = (float4*)&g_comb[(long)(b * 4096 + p) * 512 + c];
    float4 d = *dst;
    d.x = to_tf32(d.x + w00 * v00.x + w01 * v01.x + w10 * v10.x + w11 * v11.x);
    d.y = to_tf32(d.y + w00 * v00.y + w01 * v01.y + w10 * v10.y + w11 * v11.y);
    d.z = to_tf32(d.z + w00 * v00.z + w01 * v01.z + w10 * v10.z + w11 * v11.z);
    d.w = to_tf32(d.w + w00 * v00.w + w01 * v01.w + w10 * v10.w + w11 * v11.w);
    *dst = d;
}

// ---------------- launch (dual-stream: lo-GEMM + lo_attn on s2, overlap flash) ----------------
extern "C" void kernel_launch(void* const* d_in, const int* in_sizes, int n_in,
                              void* d_out, int out_size) {
    const float* x     = (const float*)d_in[0];
    const float* Wqkv  = (const float*)d_in[1];
    const float* Wproj = (const float*)d_in[2];
    const float* bproj = (const float*)d_in[3];
    float* out = (float*)d_out;

    float *xhi, *qkvhi, *win, *qkvlo, *comb, *wqr, *wpr;
    cudaGetSymbolAddress((void**)&xhi,   g_xhi);
    cudaGetSymbolAddress((void**)&qkvhi, g_qkv_hi);
    cudaGetSymbolAddress((void**)&win,   g_win);
    cudaGetSymbolAddress((void**)&qkvlo, g_qkv_lo);
    cudaGetSymbolAddress((void**)&comb,  g_comb);
    cudaGetSymbolAddress((void**)&wqr,   g_wq_r);
    cudaGetSymbolAddress((void**)&wpr,   g_wp_r);

    cudaFuncSetAttribute(mma_gemm<false>, cudaFuncAttributeMaxDynamicSharedMemorySize, GEMM_SMEM);
    cudaFuncSetAttribute(mma_gemm<true>,  cudaFuncAttributeMaxDynamicSharedMemorySize, GEMM_SMEM);
    cudaFuncSetAttribute(flash_hi_tc,     cudaFuncAttributeMaxDynamicSharedMemorySize, FLASH_SMEM);

    static cudaStream_t s2 = nullptr;
    static cudaEvent_t evFork = nullptr, evJoin = nullptr;
    if (s2 == nullptr) {
        cudaStreamCreateWithFlags(&s2, cudaStreamNonBlocking);
        cudaEventCreateWithFlags(&evFork, cudaEventDisableTiming);
        cudaEventCreateWithFlags(&evJoin, cudaEventDisableTiming);
    }

    // 0. weight rounding + prep (main stream)
    round_w_kernel<<<1024, 256>>>(Wqkv, Wproj);
    prep_kernel<<<4096, 256>>>(x);

    // fork: lo QKV GEMM then lo attention on side stream
    cudaEventRecord(evFork, 0);
    cudaStreamWaitEvent(s2, evFork, 0);
    mma_gemm<false><<<dim3(12, 256), 256, GEMM_SMEM, s2>>>(win, wqr, nullptr, qkvlo, 32768, 1536, 512);
    lo_attn_only_kernel<<<8192, 256, 0, s2>>>();
    cudaEventRecord(evJoin, s2);

    // main stream: hi QKV GEMM -> flash attention
    mma_gemm<false><<<dim3(12, 64), 256, GEMM_SMEM>>>(xhi, wqr, nullptr, qkvhi, 8192, 1536, 512);
    flash_hi_tc<<<dim3(8, 64), 256, FLASH_SMEM>>>();

    // join, then upsample-add and output projection
    cudaStreamWaitEvent(0, evJoin, 0);
    upsample_add_kernel<<<32768, 128>>>();
    mma_gemm<true><<<dim3(4, 256), 256, GEMM_SMEM>>>(comb, wpr, bproj, out, 32768, 512, 512);
}

// round 16
// speedup vs baseline: 1.1949x; 1.0796x over previous
#include <cuda_runtime.h>
#include <math.h>
#include <stdint.h>

// ---------------- problem constants ----------------
#define B_    8
#define N_    4096      // tokens per batch (64x64)
#define C_    512
#define NH_   8         // heads
#define HD_   64        // head dim
#define SCALE 0.125f    // hd^-0.5

// ---------------- scratch (device globals; no allocation allowed) ----------------
__device__ float g_xhi   [B_*1024*C_];     //  16 MB  pooled tokens (tf32-rounded)
__device__ float g_qkv_hi[B_*1024*3*C_];   //  50 MB
__device__ float g_out_hi[B_*1024*C_];     //  16 MB
__device__ float g_win   [B_*N_*C_];       //  64 MB  window tokens (tf32-rounded)
__device__ float g_qkv_lo[B_*N_*3*C_];     // 201 MB
__device__ float g_comb  [B_*N_*C_];       //  64 MB  out_lo, then out_lo+hi (tf32)
__device__ float g_wq_r  [3*C_*C_];        //   3 MB  Wqkv tf32-rounded
__device__ float g_wp_r  [C_*C_];          //   1 MB  Wproj tf32-rounded

// ======================= PTX helpers =======================
__device__ __forceinline__ uint32_t smem_u32(const void* p) {
    uint32_t a;
    asm("{ .reg .u64 t; cvta.to.shared.u64 t, %1; cvt.u32.u64 %0, t; }" : "=r"(a) : "l"(p));
    return a;
}
__device__ __forceinline__ float to_tf32(float x) {
    float r;
    asm("cvt.rna.tf32.f32 %0, %1;" : "=f"(r) : "f"(x));
    return r;
}

#define LDSM4(d0, d1, d2, d3, addr)                                            \
    asm volatile("ldmatrix.sync.aligned.m8n8.x4.shared.b16 {%0,%1,%2,%3}, [%4];" \
                 : "=r"(d0), "=r"(d1), "=r"(d2), "=r"(d3) : "r"(addr))

#define MMA_TF32(c, a, b)                                                      \
    asm volatile("mma.sync.aligned.m16n8k8.row.col.f32.tf32.tf32.f32 "         \
                 "{%0,%1,%2,%3}, {%4,%5,%6,%7}, {%8,%9}, {%0,%1,%2,%3};"       \
                 : "+f"((c)[0]), "+f"((c)[1]), "+f"((c)[2]), "+f"((c)[3])      \
                 : "r"((a)[0]), "r"((a)[1]), "r"((a)[2]), "r"((a)[3]),         \
                   "r"((b)[0]), "r"((b)[1]))

#define STSV4(addr, x, y, z, w)                                                \
    asm volatile("st.shared.v4.b32 [%0], {%1,%2,%3,%4};"                       \
                 :: "r"(addr), "f"(x), "f"(y), "f"(z), "f"(w) : "memory")
#define STSV2(addr, x, y)                                                      \
    asm volatile("st.shared.v2.b32 [%0], {%1,%2};"                             \
                 :: "r"(addr), "f"(x), "f"(y) : "memory")
#define STSB32(addr, x)                                                        \
    asm volatile("st.shared.b32 [%0], %1;" :: "r"(addr), "f"(x) : "memory")
#define LDSV4(x, y, z, w, addr)                                                \
    asm volatile("ld.shared.v4.b32 {%0,%1,%2,%3}, [%4];"                       \
                 : "=f"(x), "=f"(y), "=f"(z), "=f"(w) : "r"(addr))
#define CP_ASYNC16(dst, src)                                                   \
    asm volatile("cp.async.cg.shared.global [%0], [%1], 16;"                   \
                 :: "r"(dst), "l"(src) : "memory")
#define CP_COMMIT()  asm volatile("cp.async.commit_group;" ::: "memory")
#define CP_WAIT0()   asm volatile("cp.async.wait_group 0;" ::: "memory")
#define CP_WAIT1()   asm volatile("cp.async.wait_group 1;" ::: "memory")

// ======================= mma.sync tf32 GEMM v3 (3-stage ring) =======================
#define GEMM_SMEM (1024 + 3 * 32768)

template <bool BIAS>
__global__ void __launch_bounds__(256, 2) mma_gemm(
    const float* __restrict__ A, const float* __restrict__ Bm,
    const float* __restrict__ bias, float* __restrict__ Cm,
    int M, int N, int K)
{
    extern __shared__ char dsm[];
    uint32_t sb = (smem_u32(dsm) + 1023u) & ~1023u;

    const int t = threadIdx.x;
    const int bm = blockIdx.y, bn = blockIdx.x;
    const int lane = t & 31, wid = t >> 5;
    const int warp_m = wid & 1, warp_n = wid >> 1;

    const int f4 = t & 7;
    const int row0 = t >> 3;
    const float* Ap = A  + (long)(bm * 128 + row0) * K + f4 * 4;
    const float* Bp = Bm + (long)(bn * 128 + row0) * K + f4 * 4;
    uint32_t stOff[4];
#pragma unroll
    for (int g = 0; g < 4; g++) {
        uint32_t off = (row0 + 32 * g) * 128 + f4 * 16;
        stOff[g] = off ^ ((off >> 3) & 0x70);
    }

    const int l = lane & 7, g8 = lane >> 3;
    const int aRow = warp_m * 64 + (g8 & 1) * 8 + l;
    const uint32_t aSw   = (uint32_t)((aRow & 7) << 4);
    const uint32_t aKoff = (uint32_t)((g8 >> 1) * 16);
    const int bRow = warp_n * 32 + (g8 >> 1) * 8 + l;
    const uint32_t bSw   = (uint32_t)((bRow & 7) << 4);
    const uint32_t bKoff = (uint32_t)((g8 & 1) * 16);

    float acc[4][4][4];
#pragma unroll
    for (int mi = 0; mi < 4; mi++)
#pragma unroll
        for (int ni = 0; ni < 4; ni++)
#pragma unroll
            for (int q = 0; q < 4; q++) acc[mi][ni][q] = 0.f;

    const int KC = K >> 5;

#pragma unroll
    for (int s = 0; s < 2; s++) {
        uint32_t sA = sb + (uint32_t)s * 32768u, sB = sA + 16384;
        const float* An = Ap + s * 32;
        const float* Bn = Bp + s * 32;
#pragma unroll
        for (int g = 0; g < 4; g++) {
            CP_ASYNC16(sA + stOff[g], An + (long)(g * 32) * K);
            CP_ASYNC16(sB + stOff[g], Bn + (long)(g * 32) * K);
        }
        CP_COMMIT();
    }

    int stage = 0;
    for (int c = 0; c < KC; c++) {
        if (c + 1 < KC) { CP_WAIT1(); } else { CP_WAIT0(); }
        __syncthreads();

        uint32_t bufA = sb + (uint32_t)stage * 32768u;
        uint32_t bufB = bufA + 16384;
#pragma unroll
        for (int kk = 0; kk < 4; kk++) {
            uint32_t aOff = ((uint32_t)(kk * 32) + aKoff) ^ aSw;
            uint32_t bOff = ((uint32_t)(kk * 32) + bKoff) ^ bSw;
            uint32_t af[4][4], bf[4][2];
#pragma unroll
            for (int mi = 0; mi < 4; mi++)
                LDSM4(af[mi][0], af[mi][1], af[mi][2], af[mi][3],
                      bufA + (uint32_t)((aRow + mi * 16) * 128) + aOff);
#pragma unroll
            for (int j = 0; j < 2; j++) {
                uint32_t r0, r1, r2, r3;
                LDSM4(r0, r1, r2, r3,
                      bufB + (uint32_t)((bRow + j * 16) * 128) + bOff);
                bf[2 * j][0] = r0;     bf[2 * j][1] = r1;
                bf[2 * j + 1][0] = r2; bf[2 * j + 1][1] = r3;
            }
#pragma unroll
            for (int mi = 0; mi < 4; mi++)
#pragma unroll
                for (int ni = 0; ni < 4; ni++)
                    MMA_TF32(acc[mi][ni], af[mi], bf[ni]);
        }

        if (c + 2 < KC) {
            int ns = stage + 2; if (ns >= 3) ns -= 3;
            uint32_t sA = sb + (uint32_t)ns * 32768u, sB = sA + 16384;
            const float* An = Ap + (c + 2) * 32;
            const float* Bn = Bp + (c + 2) * 32;
#pragma unroll
            for (int g = 0; g < 4; g++) {
                CP_ASYNC16(sA + stOff[g], An + (long)(g * 32) * K);
                CP_ASYNC16(sB + stOff[g], Bn + (long)(g * 32) * K);
            }
            CP_COMMIT();
        }
        if (++stage == 3) stage = 0;
    }

    const int qr = lane >> 2, qc = lane & 3;
#pragma unroll
    for (int mi = 0; mi < 4; mi++) {
        int row = bm * 128 + warp_m * 64 + mi * 16 + qr;
#pragma unroll
        for (int ni = 0; ni < 4; ni++) {
            int col = bn * 128 + warp_n * 32 + ni * 8 + qc * 2;
            float bx = 0.f, by = 0.f;
            if (BIAS) { float2 b2 = *(const float2*)&bias[col]; bx = b2.x; by = b2.y; }
            *(float2*)&Cm[(long)row * N + col] =
                make_float2(acc[mi][ni][0] + bx, acc[mi][ni][1] + by);
            *(float2*)&Cm[(long)(row + 8) * N + col] =
                make_float2(acc[mi][ni][2] + bx, acc[mi][ni][3] + by);
        }
    }
}

// ---------------- weight rounding (Wqkv + Wproj -> tf32) ----------------
__global__ void round_w_kernel(const float* __restrict__ wq, const float* __restrict__ wp) {
    int i = blockIdx.x * blockDim.x + threadIdx.x;
    if (i < 196608) {
        float4 v = ((const float4*)wq)[i];
        ((float4*)g_wq_r)[i] = make_float4(to_tf32(v.x), to_tf32(v.y), to_tf32(v.z), to_tf32(v.w));
    } else {
        float4 v = ((const float4*)wp)[i - 196608];
        ((float4*)g_wp_r)[i - 196608] = make_float4(to_tf32(v.x), to_tf32(v.y), to_tf32(v.z), to_tf32(v.w));
    }
}

// ---------------- prep v2: vectorized avg-pool + window gather ----------------
__global__ void __launch_bounds__(256) prep_kernel(const float* __restrict__ x) {
    int id = blockIdx.x * blockDim.x + threadIdx.x;
    int c4 = (id & 127) << 2;
    int w  = (id >> 7) & 1023;
    int b  = id >> 17;
    int hh = w >> 5, wh = w & 31;

    long r0 = (long)(b * 4096 + (2 * hh) * 64 + 2 * wh) * 512 + c4;
    float4 a00 = *(const float4*)&x[r0];
    float4 a01 = *(const float4*)&x[r0 + 512];
    float4 a10 = *(const float4*)&x[r0 + 64 * 512];
    float4 a11 = *(const float4*)&x[r0 + 65 * 512];

    float4 pool;
    pool.x = to_tf32(0.25f * (a00.x + a01.x + a10.x + a11.x));
    pool.y = to_tf32(0.25f * (a00.y + a01.y + a10.y + a11.y));
    pool.z = to_tf32(0.25f * (a00.z + a01.z + a10.z + a11.z));
    pool.w = to_tf32(0.25f * (a00.w + a01.w + a10.w + a11.w));
    *(float4*)&g_xhi[(long)(b * 1024 + w) * 512 + c4] = pool;

    int t = c4 >> 7;
    int c = (4 * c4) & 511;
    float* wr = &g_win[(long)((b * 1024 + w) * 4 + t) * 512 + c];
    *(float4*)(wr + 0)  = make_float4(to_tf32(a00.x), to_tf32(a01.x), to_tf32(a10.x), to_tf32(a11.x));
    *(float4*)(wr + 4)  = make_float4(to_tf32(a00.y), to_tf32(a01.y), to_tf32(a10.y), to_tf32(a11.y));
    *(float4*)(wr + 8)  = make_float4(to_tf32(a00.z), to_tf32(a01.z), to_tf32(a10.z), to_tf32(a11.z));
    *(float4*)(wr + 12) = make_float4(to_tf32(a00.w), to_tf32(a01.w), to_tf32(a10.w), to_tf32(a11.w));
}

// ======================= flash attention v8: direct cp.async K (double-buffered) =======================
// grid (8 q-tiles, 64 bh), 256 threads = 8 warps; warp w owns q-rows 16w..16w+15 (Br=128).
// K goes cp.async -> swizzled KH[2] directly (raw fp32; HMMA truncates to tf32 in HW).
// V keeps raw+transpose+cvt; P keeps cvt. Q scratch uses PS region.
// smem: KH0 16K | KH1 16K | V^T 16K | PS 32K (also Q scratch) | rawV 17408
#define FL_VS   32768
#define FL_PS   49152
#define FL_RAWV 81920
#define FLASH_SMEM (81920 + 17408 + 1024)

__global__ void __launch_bounds__(256, 1) flash_hi_tc() {
    extern __shared__ char fsm[];
    uint32_t sb = (smem_u32(fsm) + 1023u) & ~1023u;
    const uint32_t VS = sb + FL_VS, PS = sb + FL_PS, RV = sb + FL_RAWV;

    const int t = threadIdx.x, lane = t & 31, wid = t >> 5;
    const int qt = blockIdx.x, bh = blockIdx.y;
    const int b = bh >> 3, h = bh & 7;

    // staging geometry
    const int krow = t >> 2, kq4 = t & 3;            // K: 64 tokens x 4 chunks of 64B
    const uint32_t ksw = (uint32_t)((krow & 7) << 4);
    const int vtok = t & 63, vdb = (t >> 6) * 16;    // V: 64 toks x 16-d blocks
    const uint32_t rvd = RV + (uint32_t)(vtok * 272 + vdb * 4);
    const float* kv_base = g_qkv_hi + (long)(b * 1024) * 1536 + 512 + h * 64;

    // issue tile 0: K -> KH0 (swizzled), V -> rawV
    {
        const float* kg = kv_base + (long)krow * 1536 + kq4 * 16;
        const float* vg = kv_base + (long)vtok * 1536 + 512 + vdb;
        uint32_t kdst = sb + (uint32_t)(krow * 256);
#pragma unroll
        for (int i = 0; i < 4; i++) {
            CP_ASYNC16(kdst + (((uint32_t)(kq4 * 64 + i * 16)) ^ ksw), kg + i * 4);
            CP_ASYNC16(rvd + i * 16, vg + i * 4);
        }
        CP_COMMIT();
    }

    // ---- fragment geometry ----
    const int l7 = lane & 7, g8 = lane >> 3;
    const int aRow = wid * 16 + (g8 & 1) * 8 + l7;
    const uint32_t aKsel = (uint32_t)((g8 >> 1) * 16);
    const int bRow = (g8 >> 1) * 8 + l7;
    const uint32_t bKsel = (uint32_t)((g8 & 1) * 16);
    const uint32_t swl = (uint32_t)(l7 << 4);
    const int qr = lane >> 2, qc = lane & 3;

    // ---- Q fragments into registers (PS region as scratch) ----
    uint32_t qh[8][4];
    {
        int row = t >> 1, hb = t & 1;
        const float* qg = g_qkv_hi + (long)(b * 1024 + qt * 128 + row) * 1536 + h * 64 + hb * 32;
        uint32_t rbase = PS + (uint32_t)(row * 256);
        uint32_t rsw = (uint32_t)((row & 7) << 4);
#pragma unroll
        for (int i = 0; i < 8; i++) {
            float4 v = *(const float4*)(qg + i * 4);
            v.x *= SCALE; v.y *= SCALE; v.z *= SCALE; v.w *= SCALE;
            uint32_t off = ((uint32_t)(hb * 128 + i * 16)) ^ rsw;
            STSV4(rbase + off, to_tf32(v.x), to_tf32(v.y), to_tf32(v.z), to_tf32(v.w));
        }
        __syncthreads();
#pragma unroll
        for (int kk = 0; kk < 8; kk++)
            LDSM4(qh[kk][0], qh[kk][1], qh[kk][2], qh[kk][3],
                  PS + (uint32_t)(aRow * 256) + (((uint32_t)(kk * 32) + aKsel) ^ swl));
    }

    float oacc[8][4];
#pragma unroll
    for (int ni = 0; ni < 8; ni++)
#pragma unroll
        for (int q = 0; q < 4; q++) oacc[ni][q] = 0.f;
    float l0 = 0.f, l1 = 0.f;

    for (int kt = 0; kt < 16; kt++) {
        CP_WAIT0();
        __syncthreads();   // tile kt visible (KH[kt&1], rawV); all prior readers done

        const uint32_t KH = sb + (uint32_t)((kt & 1) * 16384);

        // ---- convert raw V -> V^T (lane-distinct tokens; keeps cvt) ----
        {
            uint32_t tokb = (uint32_t)(vtok * 4);
#pragma unroll
            for (int i = 0; i < 4; i++) {
                float x_, y_, z_, w_;
                LDSV4(x_, y_, z_, w_, rvd + i * 16);
                int d0 = vdb + i * 4;
                STSB32(VS + (uint32_t)((d0 + 0) * 256) + (tokb ^ (uint32_t)(((d0 + 0) & 7) << 4)), to_tf32(x_));
                STSB32(VS + (uint32_t)((d0 + 1) * 256) + (tokb ^ (uint32_t)(((d0 + 1) & 7) << 4)), to_tf32(y_));
                STSB32(VS + (uint32_t)((d0 + 2) * 256) + (tokb ^ (uint32_t)(((d0 + 2) & 7) << 4)), to_tf32(z_));
                STSB32(VS + (uint32_t)((d0 + 3) * 256) + (tokb ^ (uint32_t)(((d0 + 3) & 7) << 4)), to_tf32(w_));
            }
        }
        // ---- issue tile kt+1: K -> KH[(kt+1)&1], V -> rawV ----
        if (kt + 1 < 16) {
            const float* kg = kv_base + (long)((kt + 1) * 64 + krow) * 1536 + kq4 * 16;
            const float* vg = kv_base + (long)((kt + 1) * 64 + vtok) * 1536 + 512 + vdb;
            uint32_t kdst = sb + (uint32_t)(((kt + 1) & 1) * 16384 + krow * 256);
#pragma unroll
            for (int i = 0; i < 4; i++) {
                CP_ASYNC16(kdst + (((uint32_t)(kq4 * 64 + i * 16)) ^ ksw), kg + i * 4);
                CP_ASYNC16(rvd + i * 16, vg + i * 4);
            }
            CP_COMMIT();
        }
        __syncthreads();   // VS writes visible; PS free (prior iter's PV reads done at barrier 1)

        // ---- S = Q K^T (K raw fp32 -> HW tf32 truncation) ----
        float sacc[8][4];
#pragma unroll
        for (int ni = 0; ni < 8; ni++)
#pragma unroll
            for (int q = 0; q < 4; q++) sacc[ni][q] = 0.f;

#pragma unroll
        for (int kk = 0; kk < 8; kk++) {
            uint32_t bOff = ((uint32_t)(kk * 32) + bKsel) ^ swl;
#pragma unroll
            for (int j = 0; j < 4; j++) {
                uint32_t r0, r1, r2, r3;
                LDSM4(r0, r1, r2, r3, KH + (uint32_t)((bRow + j * 16) * 256) + bOff);
                uint32_t bh0[2] = {r0, r1}, bh1[2] = {r2, r3};
                MMA_TF32(sacc[2 * j],     qh[kk], bh0);
                MMA_TF32(sacc[2 * j + 1], qh[kk], bh1);
            }
        }

        // ---- P = exp(S) (no-max softmax; logits bounded) ----
        float rs0 = 0.f, rs1 = 0.f;
        const uint32_t pr0 = PS + (uint32_t)((wid * 16 + qr) * 256);
        const uint32_t pr1 = PS + (uint32_t)((wid * 16 + qr + 8) * 256);
        const uint32_t sw0 = (uint32_t)((qr & 7) << 4);
        const uint32_t sw1 = (uint32_t)(((qr + 8) & 7) << 4);
#pragma unroll
        for (int ni = 0; ni < 8; ni++) {
            float q0 = to_tf32(__expf(sacc[ni][0]));
            float q1 = to_tf32(__expf(sacc[ni][1]));
            float q2 = to_tf32(__expf(sacc[ni][2]));
            float q3 = to_tf32(__expf(sacc[ni][3]));
            rs0 += q0 + q1; rs1 += q2 + q3;
            uint32_t cb = (uint32_t)(ni * 32 + qc * 8);
            STSV2(pr0 + (cb ^ sw0), q0, q1);
            STSV2(pr1 + (cb ^ sw1), q2, q3);
        }
        rs0 += __shfl_xor_sync(0xffffffffu, rs0, 1);
        rs0 += __shfl_xor_sync(0xffffffffu, rs0, 2);
        rs1 += __shfl_xor_sync(0xffffffffu, rs1, 1);
        rs1 += __shfl_xor_sync(0xffffffffu, rs1, 2);
        l0 += rs0; l1 += rs1;
        __syncwarp();   // P rows are warp-private

        // ---- O += P V ----
#pragma unroll
        for (int kk = 0; kk < 8; kk++) {
            uint32_t kb = (uint32_t)(kk * 32);
            uint32_t ap[4];
            LDSM4(ap[0], ap[1], ap[2], ap[3],
                  PS + (uint32_t)(aRow * 256) + ((kb + aKsel) ^ swl));
            uint32_t bOff = (kb + bKsel) ^ swl;
#pragma unroll
            for (int j = 0; j < 4; j++) {
                uint32_t r0, r1, r2, r3;
                LDSM4(r0, r1, r2, r3, VS + (uint32_t)((bRow + j * 16) * 256) + bOff);
                uint32_t bv0[2] = {r0, r1}, bv1[2] = {r2, r3};
                MMA_TF32(oacc[2 * j],     ap, bv0);
                MMA_TF32(oacc[2 * j + 1], ap, bv1);
            }
        }
    }

    float inv0 = 1.f / l0, inv1 = 1.f / l1;
    long r0g = (long)(b * 1024 + qt * 128 + wid * 16 + qr) * 512 + h * 64;
    long r1g = r0g + 8 * 512;
#pragma unroll
    for (int ni = 0; ni < 8; ni++) {
        int col = ni * 8 + qc * 2;
        *(float2*)&g_out_hi[r0g + col] = make_float2(oacc[ni][0] * inv0, oacc[ni][1] * inv0);
        *(float2*)&g_out_hi[r1g + col] = make_float2(oacc[ni][2] * inv1, oacc[ni][3] * inv1);
    }
}

// ---------------- lo-branch windowed attention ONLY (unrounded out_lo -> g_comb) ----------------
__global__ void __launch_bounds__(256) lo_attn_only_kernel() {
    int gid  = blockIdx.x * blockDim.x + threadIdx.x;
    int warp = gid >> 5;
    int lane = gid & 31;
    int h = warp & 7;
    int w = (warp >> 3) & 1023;
    int b = warp >> 13;

    const float* base = g_qkv_lo + (long)((b * 1024 + w) * 4) * 1536 + h * 64 + 2 * lane;
    float2 q[4], k[4], v[4];
#pragma unroll
    for (int t = 0; t < 4; t++) {
        q[t] = *(const float2*)(base + (long)t * 1536);
        k[t] = *(const float2*)(base + (long)t * 1536 + 512);
        v[t] = *(const float2*)(base + (long)t * 1536 + 1024);
    }

    float lg[4][4];
#pragma unroll
    for (int ti = 0; ti < 4; ti++)
#pragma unroll
        for (int tj = 0; tj < 4; tj++) {
            float p = q[ti].x * k[tj].x + q[ti].y * k[tj].y;
            p += __shfl_xor_sync(0xffffffffu, p, 16);
            p += __shfl_xor_sync(0xffffffffu, p, 8);
            p += __shfl_xor_sync(0xffffffffu, p, 4);
            p += __shfl_xor_sync(0xffffffffu, p, 2);
            p += __shfl_xor_sync(0xffffffffu, p, 1);
            lg[ti][tj] = p * SCALE;
        }

    int hh = w >> 5, wh = w & 31;
    int ccol = h * 64 + 2 * lane;
#pragma unroll
    for (int ti = 0; ti < 4; ti++) {
        float mx = fmaxf(fmaxf(lg[ti][0], lg[ti][1]), fmaxf(lg[ti][2], lg[ti][3]));
        float e0 = __expf(lg[ti][0] - mx);
        float e1 = __expf(lg[ti][1] - mx);
        float e2 = __expf(lg[ti][2] - mx);
        float e3 = __expf(lg[ti][3] - mx);
        float is = 1.f / (e0 + e1 + e2 + e3);
        float ox = (e0 * v[0].x + e1 * v[1].x + e2 * v[2].x + e3 * v[3].x) * is;
        float oy = (e0 * v[0].y + e1 * v[1].y + e2 * v[2].y + e3 * v[3].y) * is;

        int pos = (2 * hh + (ti >> 1)) * 64 + 2 * wh + (ti & 1);
        *(float2*)&g_comb[(long)(b * 4096 + pos) * 512 + ccol] = make_float2(ox, oy);
    }
}

// ---------------- bilinear upsample 32->64 + add (final tf32 round) ----------------
__global__ void __launch_bounds__(128) upsample_add_kernel() {
    int blk = blockIdx.x;
    int b = blk >> 12;
    int p = blk & 4095;
    int y = p >> 6, xq = p & 63;

    float sy = 0.5f * y - 0.25f;
    int   y0 = (int)floorf(sy);
    float fy = sy - (float)y0;
    int   y1 = min(y0 + 1, 31); y0 = max(y0, 0);

    float sx = 0.5f * xq - 0.25f;
    int   x0 = (int)floorf(sx);
    float fx = sx - (float)x0;
    int   x1 = min(x0 + 1, 31); x0 = max(x0, 0);

    float w00 = (1.f - fy) * (1.f - fx), w01 = (1.f - fy) * fx;
    float w10 = fy * (1.f - fx),         w11 = fy * fx;

    int c = threadIdx.x * 4;
    long base = (long)b * 1024 * 512;
    float4 v00 = *(const float4*)&g_out_hi[base + (long)(y0 * 32 + x0) * 512 + c];
    float4 v01 = *(const float4*)&g_out_hi[base + (long)(y0 * 32 + x1) * 512 + c];
    float4 v10 = *(const float4*)&g_out_hi[base + (long)(y1 * 32 + x0) * 512 + c];
    float4 v11 = *(const float4*)&g_out_hi[base + (long)(y1 * 32 + x1) * 512 + c];

    float4* dst = (float4*)&g_comb[(long)(b * 4096 + p) * 512 + c];
    float4 d = *dst;
    d.x = to_tf32(d.x + w00 * v00.x + w01 * v01.x + w10 * v10.x + w11 * v11.x);
    d.y = to_tf32(d.y + w00 * v00.y + w01 * v01.y + w10 * v10.y + w11 * v11.y);
    d.z = to_tf32(d.z + w00 * v00.z + w01 * v01.z + w10 * v10.z + w11 * v11.z);
    d.w = to_tf32(d.w + w00 * v00.w + w01 * v01.w + w10 * v10.w + w11 * v11.w);
    *dst = d;
}

// ---------------- launch (capture-legal fork: s2 joins via event BEFORE any s2 work) ----------------
extern "C" void kernel_launch(void* const* d_in, const int* in_sizes, int n_in,
                              void* d_out, int out_size) {
    const float* x     = (const float*)d_in[0];
    const float* Wqkv  = (const float*)d_in[1];
    const float* Wproj = (const float*)d_in[2];
    const float* bproj = (const float*)d_in[3];
    float* out = (float*)d_out;

    float *xhi, *qkvhi, *win, *qkvlo, *comb, *wqr, *wpr;
    cudaGetSymbolAddress((void**)&xhi,   g_xhi);
    cudaGetSymbolAddress((void**)&qkvhi, g_qkv_hi);
    cudaGetSymbolAddress((void**)&win,   g_win);
    cudaGetSymbolAddress((void**)&qkvlo, g_qkv_lo);
    cudaGetSymbolAddress((void**)&comb,  g_comb);
    cudaGetSymbolAddress((void**)&wqr,   g_wq_r);
    cudaGetSymbolAddress((void**)&wpr,   g_wp_r);

    cudaFuncSetAttribute(mma_gemm<false>, cudaFuncAttributeMaxDynamicSharedMemorySize, GEMM_SMEM);
    cudaFuncSetAttribute(mma_gemm<true>,  cudaFuncAttributeMaxDynamicSharedMemorySize, GEMM_SMEM);
    cudaFuncSetAttribute(flash_hi_tc,     cudaFuncAttributeMaxDynamicSharedMemorySize, FLASH_SMEM);

    static cudaStream_t s2 = nullptr;
    static cudaEvent_t evFork = nullptr, evPrep = nullptr, evJoin = nullptr, evW = nullptr;
    if (s2 == nullptr) {
        cudaStreamCreateWithFlags(&s2, cudaStreamNonBlocking);
        cudaEventCreateWithFlags(&evFork, cudaEventDisableTiming);
        cudaEventCreateWithFlags(&evPrep, cudaEventDisableTiming);
        cudaEventCreateWithFlags(&evJoin, cudaEventDisableTiming);
        cudaEventCreateWithFlags(&evW,    cudaEventDisableTiming);
    }

    // fork s2 into the capture graph FIRST (origin-stream event -> s2 wait)
    cudaEventRecord(evFork, 0);
    cudaStreamWaitEvent(s2, evFork, 0);

    // s2: weight rounding (concurrent with prep on main)
    round_w_kernel<<<1024, 256, 0, s2>>>(Wqkv, Wproj);
    cudaEventRecord(evW, s2);

    // main: prep
    prep_kernel<<<4096, 256>>>(x);
    cudaEventRecord(evPrep, 0);

    // s2: lo QKV GEMM (after prep) then lo attention
    cudaStreamWaitEvent(s2, evPrep, 0);
    mma_gemm<false><<<dim3(12, 256), 256, GEMM_SMEM, s2>>>(win, wqr, nullptr, qkvlo, 32768, 1536, 512);
    lo_attn_only_kernel<<<8192, 256, 0, s2>>>();
    cudaEventRecord(evJoin, s2);

    // main: wait for weights, hi QKV GEMM -> flash attention
    cudaStreamWaitEvent(0, evW, 0);
    mma_gemm<false><<<dim3(12, 64), 256, GEMM_SMEM>>>(xhi, wqr, nullptr, qkvhi, 8192, 1536, 512);
    flash_hi_tc<<<dim3(8, 64), 256, FLASH_SMEM>>>();

    // join, then upsample-add and output projection
    cudaStreamWaitEvent(0, evJoin, 0);
    upsample_add_kernel<<<32768, 128>>>();
    mma_gemm<true><<<dim3(4, 256), 256, GEMM_SMEM>>>(comb, wpr, bproj, out, 32768, 512, 512);
}